// round 7
// baseline (speedup 1.0000x reference)
#include <cuda_runtime.h>
#include <cuda_bf16.h>
#include <cstdint>
#include <cstddef>

#define TSTEPS 512
#define NBATCH 64
#define HID    1024
#define NGATE  4096
#define TBROWS (TSTEPS * NBATCH)          // 32768
#define GH     (NGATE * HID)              // 4194304

typedef __nv_bfloat16 bf16;

// ---------------- static device scratch (no runtime allocation) -------------
__device__ float    g_xw[(size_t)TBROWS * NGATE];     // 536 MB, per-layer reuse
__device__ bf16     g_ahi[(size_t)TBROWS * HID];      // x splits -> h1 -> h2
__device__ bf16     g_alo[(size_t)TBROWS * HID];
__device__ bf16     g_whi[4ull * GH];                 // wih0, whh0, wih1, whh1
__device__ bf16     g_wlo[4ull * GH];
__device__ float    g_bias[2 * NGATE];
__device__ unsigned g_barcnt;                         // monotonic grid barrier

// ---------------- helpers ---------------------------------------------------
static __device__ __forceinline__ uint32_t sptr(const void* p) {
    return (uint32_t)__cvta_generic_to_shared(p);
}
static __device__ __forceinline__ void ldsm4(uint32_t* r, uint32_t a) {
    asm volatile("ldmatrix.sync.aligned.m8n8.x4.shared.b16 {%0,%1,%2,%3}, [%4];\n"
                 : "=r"(r[0]), "=r"(r[1]), "=r"(r[2]), "=r"(r[3]) : "r"(a));
}
static __device__ __forceinline__ void mma_nt(float* d, const uint32_t* a,
                                              uint32_t b0, uint32_t b1) {
    asm volatile(
        "mma.sync.aligned.m16n8k16.row.col.f32.bf16.bf16.f32 "
        "{%0,%1,%2,%3},{%4,%5,%6,%7},{%8,%9},{%0,%1,%2,%3};\n"
        : "+f"(d[0]), "+f"(d[1]), "+f"(d[2]), "+f"(d[3])
        : "r"(a[0]), "r"(a[1]), "r"(a[2]), "r"(a[3]), "r"(b0), "r"(b1));
}
static __device__ __forceinline__ void cpa16(uint32_t dst, const void* src) {
    asm volatile("cp.async.cg.shared.global [%0], [%1], 16;\n" :: "r"(dst), "l"(src));
}
#define CP_COMMIT() asm volatile("cp.async.commit_group;\n")
#define CP_WAIT1()  asm volatile("cp.async.wait_group 1;\n")
#define CP_WAIT0()  asm volatile("cp.async.wait_group 0;\n")
static __device__ __forceinline__ float sigf(float x) { return 1.f / (1.f + expf(-x)); }

// One BK=32 tile of 3-term split MMA work (ldsm from 6 smem bases).
static __device__ __forceinline__ void compute_tile(
    uint32_t aHiA, uint32_t aLoA, uint32_t bHiA0, uint32_t bHiA1,
    uint32_t bLoA0, uint32_t bLoA1, float acc[4][4]) {
#pragma unroll
    for (int kk = 0; kk < 2; ++kk) {
        const uint32_t ko = kk * 32;
        uint32_t ah[4], al[4], bh0[4], bh1[4], bl0[4], bl1[4];
        ldsm4(ah, aHiA + ko);   ldsm4(al, aLoA + ko);
        ldsm4(bh0, bHiA0 + ko); ldsm4(bh1, bHiA1 + ko);
        ldsm4(bl0, bLoA0 + ko); ldsm4(bl1, bLoA1 + ko);
        mma_nt(acc[0], ah, bh0[0], bh0[2]); mma_nt(acc[0], ah, bl0[0], bl0[2]);
        mma_nt(acc[0], al, bh0[0], bh0[2]);
        mma_nt(acc[1], ah, bh0[1], bh0[3]); mma_nt(acc[1], ah, bl0[1], bl0[3]);
        mma_nt(acc[1], al, bh0[1], bh0[3]);
        mma_nt(acc[2], ah, bh1[0], bh1[2]); mma_nt(acc[2], ah, bl1[0], bl1[2]);
        mma_nt(acc[2], al, bh1[0], bh1[2]);
        mma_nt(acc[3], ah, bh1[1], bh1[3]); mma_nt(acc[3], ah, bl1[1], bl1[3]);
        mma_nt(acc[3], al, bh1[1], bh1[3]);
    }
}

// Grid barrier: 64 CTAs, monotonic ticket counter (replay-safe).
static __device__ __forceinline__ void grid_barrier() {
    __syncthreads();
    if (threadIdx.x == 0) {
        __threadfence();
        unsigned tk = atomicAdd(&g_barcnt, 1u);
        unsigned target = (tk & ~63u) + 64u;
        while ((int)(*(volatile unsigned*)&g_barcnt - target) < 0) {}
        __threadfence();
    }
    __syncthreads();
}

// ---------------- fp32 -> bf16 hi/lo split ----------------------------------
__global__ void split_kernel(const float* __restrict__ s, bf16* __restrict__ hi,
                             bf16* __restrict__ lo, int n) {
    for (int i = blockIdx.x * blockDim.x + threadIdx.x; i < n; i += gridDim.x * blockDim.x) {
        float v = s[i];
        bf16 h = __float2bfloat16(v);
        hi[i] = h;
        lo[i] = __float2bfloat16(v - __bfloat162float(h));
    }
}
__global__ void bias_kernel(const float* __restrict__ a, const float* __restrict__ b,
                            float* __restrict__ o, int n) {
    int i = blockIdx.x * blockDim.x + threadIdx.x;
    if (i < n) o[i] = a[i] + b[i];
}

// ---------------- big GEMM: out[M,4096] = A[M,1024] @ W[4096,1024]^T + bias --
// CTA tile 64x64, BK=32, 256 thr, cp.async double-buffered. grid=(n64, m512).
__global__ __launch_bounds__(256) void gemm_xw(
    const bf16* __restrict__ Ahi, const bf16* __restrict__ Alo,
    const bf16* __restrict__ Whi, const bf16* __restrict__ Wlo,
    const float* __restrict__ bias, float* __restrict__ out) {
    __shared__ __align__(16) unsigned char sraw[40960];   // 4 arrays x 2 stages x 5120B
    const uint32_t sb = sptr(sraw);

    const int tid = threadIdx.x, warp = tid >> 5, lane = tid & 31;
    const size_t n0 = (size_t)blockIdx.x * 64, m0 = (size_t)blockIdx.y * 64;
    const int lr = tid >> 2, lc = (tid & 3) * 8;

    const bf16* pAhi = Ahi + (m0 + lr) * HID + lc;
    const bf16* pAlo = Alo + (m0 + lr) * HID + lc;
    const bf16* pBhi = Whi + (n0 + lr) * HID + lc;
    const bf16* pBlo = Wlo + (n0 + lr) * HID + lc;
    const uint32_t stb = (uint32_t)((lr * 40 + lc) * 2);

    const int mB = (warp & 3) * 16, nB = (warp >> 2) * 32;
    const int lrow = lane & 15;
    const uint32_t lkb2 = (uint32_t)((lane >> 4) * 16);
    const uint32_t aHiB  = sb +         (uint32_t)((mB + lrow) * 80) + lkb2;
    const uint32_t aLoB  = aHiB + 10240;
    const uint32_t bHiB0 = sb + 20480 + (uint32_t)((nB + lrow) * 80) + lkb2;
    const uint32_t bHiB1 = sb + 20480 + (uint32_t)((nB + 16 + lrow) * 80) + lkb2;
    const uint32_t bLoB0 = bHiB0 + 10240;
    const uint32_t bLoB1 = bHiB1 + 10240;

    float acc[4][4];
#pragma unroll
    for (int i = 0; i < 4; ++i)
#pragma unroll
        for (int j = 0; j < 4; ++j) acc[i][j] = 0.f;

#define GEMM_ISSUE(it, s) do {                                   \
        cpa16(sb +         (s) * 5120 + stb, pAhi + (it) * 32);  \
        cpa16(sb + 10240 + (s) * 5120 + stb, pAlo + (it) * 32);  \
        cpa16(sb + 20480 + (s) * 5120 + stb, pBhi + (it) * 32);  \
        cpa16(sb + 30720 + (s) * 5120 + stb, pBlo + (it) * 32);  \
        CP_COMMIT(); } while (0)

    GEMM_ISSUE(0, 0);
    for (int it = 0; it < 32; ++it) {
        if (it < 31) { GEMM_ISSUE(it + 1, (it + 1) & 1); CP_WAIT1(); }
        else         { CP_WAIT0(); }
        __syncthreads();
        const uint32_t so = (uint32_t)((it & 1) * 5120);
        compute_tile(aHiB + so, aLoB + so, bHiB0 + so, bHiB1 + so,
                     bLoB0 + so, bLoB1 + so, acc);
        __syncthreads();
    }
#undef GEMM_ISSUE

    const size_t row0 = m0 + mB + (lane >> 2);
#pragma unroll
    for (int nb = 0; nb < 4; ++nb) {
        const size_t col = n0 + nB + nb * 8 + (lane & 3) * 2;
        const float b0 = bias[col], b1 = bias[col + 1];
        float2* o0 = (float2*)(out + row0 * NGATE + col);
        float2* o1 = (float2*)(out + (row0 + 8) * NGATE + col);
        *o0 = make_float2(acc[nb][0] + b0, acc[nb][1] + b1);
        *o1 = make_float2(acc[nb][2] + b0, acc[nb][3] + b1);
    }
}

// ---------------- persistent recurrent layer ---------------------------------
// 64 CTAs (all resident). CTA: 64 batch x 16 h-cols, all 4 gates.
// c state in registers; grid barrier between timesteps.
__global__ __launch_bounds__(256) void lstm_layer(
    const bf16* __restrict__ Whi, const bf16* __restrict__ Wlo,   // whh splits
    const float* __restrict__ xw,                                 // [512][64][4096]
    bf16* __restrict__ hHi, bf16* __restrict__ hLo,               // slot t out / t-1 in
    float* __restrict__ outF) {                                   // null for layer 0
    __shared__ __align__(16) unsigned char sraw[40960];           // pipeline ∪ sG
    float* sG = (float*)sraw;                                     // 64*65*4 = 16640B
    const uint32_t sb = sptr(sraw);

    const int tid = threadIdx.x, warp = tid >> 5, lane = tid & 31;
    const int hs = blockIdx.x * 16;
    const int lr = tid >> 2, lc = (tid & 3) * 8;
    const int wrow = (lr >> 4) * HID + hs + (lr & 15);            // gate*1024 + h-col
    const bf16* pBhi = Whi + (size_t)wrow * HID + lc;
    const bf16* pBlo = Wlo + (size_t)wrow * HID + lc;
    const uint32_t stb = (uint32_t)((lr * 40 + lc) * 2);

    const int mB = (warp & 3) * 16, nB = (warp >> 2) * 32;
    const int lrow = lane & 15;
    const uint32_t lkb2 = (uint32_t)((lane >> 4) * 16);
    const uint32_t aHiB  = sb +         (uint32_t)((mB + lrow) * 80) + lkb2;
    const uint32_t aLoB  = aHiB + 10240;
    const uint32_t bHiB0 = sb + 20480 + (uint32_t)((nB + lrow) * 80) + lkb2;
    const uint32_t bHiB1 = sb + 20480 + (uint32_t)((nB + 16 + lrow) * 80) + lkb2;
    const uint32_t bLoB0 = bHiB0 + 10240;
    const uint32_t bLoB1 = bHiB1 + 10240;

    float creg[4] = {0.f, 0.f, 0.f, 0.f};

#pragma unroll 1
    for (int t = 0; t < TSTEPS; ++t) {
        float acc[4][4];
#pragma unroll
        for (int i = 0; i < 4; ++i)
#pragma unroll
            for (int j = 0; j < 4; ++j) acc[i][j] = 0.f;

        if (t > 0) {
            const bf16* pAhi = hHi + (size_t)(t - 1) * NBATCH * HID + lr * HID + lc;
            const bf16* pAlo = hLo + (size_t)(t - 1) * NBATCH * HID + lr * HID + lc;
#define STEP_ISSUE(it, s) do {                                   \
            cpa16(sb +         (s) * 5120 + stb, pAhi + (it) * 32); \
            cpa16(sb + 10240 + (s) * 5120 + stb, pAlo + (it) * 32); \
            cpa16(sb + 20480 + (s) * 5120 + stb, pBhi + (it) * 32); \
            cpa16(sb + 30720 + (s) * 5120 + stb, pBlo + (it) * 32); \
            CP_COMMIT(); } while (0)
            STEP_ISSUE(0, 0);
            for (int it = 0; it < 32; ++it) {
                if (it < 31) { STEP_ISSUE(it + 1, (it + 1) & 1); CP_WAIT1(); }
                else         { CP_WAIT0(); }
                __syncthreads();
                const uint32_t so = (uint32_t)((it & 1) * 5120);
                compute_tile(aHiB + so, aLoB + so, bHiB0 + so, bHiB1 + so,
                             bLoB0 + so, bLoB1 + so, acc);
                __syncthreads();
            }
#undef STEP_ISSUE
        }

        // stage recurrent gate sums into smem (aliases pipeline buffers — safe:
        // last compute iteration ended with __syncthreads)
        {
            const int row0 = mB + (lane >> 2);
#pragma unroll
            for (int nb = 0; nb < 4; ++nb) {
                const int j = nB + nb * 8 + (lane & 3) * 2;
                sG[row0 * 65 + j]           = acc[nb][0];
                sG[row0 * 65 + j + 1]       = acc[nb][1];
                sG[(row0 + 8) * 65 + j]     = acc[nb][2];
                sG[(row0 + 8) * 65 + j + 1] = acc[nb][3];
            }
        }
        __syncthreads();

        // epilogue: 64 batch x 16 h-cols; c in registers
        const float* xwt = xw + (size_t)t * NBATCH * NGATE;
        const size_t obase = (size_t)t * NBATCH * HID;
#pragma unroll
        for (int k2 = 0; k2 < 4; ++k2) {
            const int e = tid + k2 * 256;
            const int m = e >> 4, j = e & 15, hc = hs + j;
            const float* xwm = xwt + (size_t)m * NGATE;
            const float ii = sG[m * 65 + j]      + xwm[hc];
            const float ff = sG[m * 65 + 16 + j] + xwm[HID + hc];
            const float gg = sG[m * 65 + 32 + j] + xwm[2 * HID + hc];
            const float oo = sG[m * 65 + 48 + j] + xwm[3 * HID + hc];
            const float c  = sigf(ff) * creg[k2] + sigf(ii) * tanhf(gg);
            const float h  = sigf(oo) * tanhf(c);
            creg[k2] = c;
            const bf16 hh = __float2bfloat16(h);
            const size_t oidx = obase + (size_t)m * HID + hc;
            hHi[oidx] = hh;
            hLo[oidx] = __float2bfloat16(h - __bfloat162float(hh));
            if (outF) outF[oidx] = h;
        }
        grid_barrier();
    }
}

// ---------------- host ------------------------------------------------------
extern "C" void kernel_launch(void* const* d_in, const int* in_sizes, int n_in,
                              void* d_out, int out_size) {
    const float* x    = (const float*)d_in[0];
    const float* wih0 = (const float*)d_in[1];
    const float* whh0 = (const float*)d_in[2];
    const float* bih0 = (const float*)d_in[3];
    const float* bhh0 = (const float*)d_in[4];
    const float* wih1 = (const float*)d_in[5];
    const float* whh1 = (const float*)d_in[6];
    const float* bih1 = (const float*)d_in[7];
    const float* bhh1 = (const float*)d_in[8];

    float *xw, *bias;
    bf16 *ahi, *alo, *whi, *wlo;
    cudaGetSymbolAddress((void**)&xw,   g_xw);
    cudaGetSymbolAddress((void**)&ahi,  g_ahi);
    cudaGetSymbolAddress((void**)&alo,  g_alo);
    cudaGetSymbolAddress((void**)&whi,  g_whi);
    cudaGetSymbolAddress((void**)&wlo,  g_wlo);
    cudaGetSymbolAddress((void**)&bias, g_bias);

    split_kernel<<<2048, 256>>>(x, ahi, alo, TBROWS * HID);
    const float* ws[4] = {wih0, whh0, wih1, whh1};
    for (int i = 0; i < 4; ++i)
        split_kernel<<<2048, 256>>>(ws[i], whi + (size_t)i * GH, wlo + (size_t)i * GH, GH);
    bias_kernel<<<16, 256>>>(bih0, bhh0, bias, NGATE);
    bias_kernel<<<16, 256>>>(bih1, bhh1, bias + NGATE, NGATE);

    for (int layer = 0; layer < 2; ++layer) {
        const size_t wih_off = (size_t)(2 * layer) * GH;
        const size_t whh_off = (size_t)(2 * layer + 1) * GH;
        gemm_xw<<<dim3(64, 512), 256>>>(ahi, alo, whi + wih_off, wlo + wih_off,
                                        bias + layer * NGATE, xw);
        lstm_layer<<<64, 256>>>(whi + whh_off, wlo + whh_off, xw, ahi, alo,
                                layer ? (float*)d_out : nullptr);
    }
}

// round 9
// speedup vs baseline: 1.4728x; 1.4728x over previous
#include <cuda_runtime.h>
#include <cuda_bf16.h>
#include <cstdint>
#include <cstddef>

#define TSTEPS 512
#define NBATCH 64
#define HID    1024
#define NGATE  4096
#define TBROWS (TSTEPS * NBATCH)          // 32768
#define GH     (NGATE * HID)              // 4194304 = 2^22
#define XLEN   ((size_t)TBROWS * HID)     // 33554432

typedef __nv_bfloat16 bf16;

// ---------------- static device scratch (no runtime allocation) -------------
__device__ float    g_xw[(size_t)TBROWS * NGATE];     // 536 MB, per-layer reuse
__device__ bf16     g_ahi[XLEN];                      // x splits -> h1 -> h2
__device__ bf16     g_alo[XLEN];
__device__ bf16     g_whi[4ull * GH];                 // wih0, whh0, wih1, whh1
__device__ bf16     g_wlo[4ull * GH];
__device__ float    g_bias[2 * NGATE];
__device__ unsigned g_barcnt;                         // monotonic grid barrier

// ---------------- helpers ---------------------------------------------------
static __device__ __forceinline__ uint32_t sptr(const void* p) {
    return (uint32_t)__cvta_generic_to_shared(p);
}
static __device__ __forceinline__ void ldsm4(uint32_t* r, uint32_t a) {
    asm volatile("ldmatrix.sync.aligned.m8n8.x4.shared.b16 {%0,%1,%2,%3}, [%4];\n"
                 : "=r"(r[0]), "=r"(r[1]), "=r"(r[2]), "=r"(r[3]) : "r"(a));
}
static __device__ __forceinline__ void mma_nt(float* d, const uint32_t* a,
                                              uint32_t b0, uint32_t b1) {
    asm volatile(
        "mma.sync.aligned.m16n8k16.row.col.f32.bf16.bf16.f32 "
        "{%0,%1,%2,%3},{%4,%5,%6,%7},{%8,%9},{%0,%1,%2,%3};\n"
        : "+f"(d[0]), "+f"(d[1]), "+f"(d[2]), "+f"(d[3])
        : "r"(a[0]), "r"(a[1]), "r"(a[2]), "r"(a[3]), "r"(b0), "r"(b1));
}
static __device__ __forceinline__ void cpa16(uint32_t dst, const void* src) {
    asm volatile("cp.async.cg.shared.global [%0], [%1], 16;\n" :: "r"(dst), "l"(src));
}
#define CP_COMMIT() asm volatile("cp.async.commit_group;\n")
#define CP_WAIT1()  asm volatile("cp.async.wait_group 1;\n")
#define CP_WAIT0()  asm volatile("cp.async.wait_group 0;\n")
static __device__ __forceinline__ float sigf(float x) { return 1.f / (1.f + expf(-x)); }

// Grid barrier over NCTA CTAs: monotonic ticket counter (graph-replay safe).
template <unsigned NCTA>
static __device__ __forceinline__ void grid_barrier() {
    __syncthreads();
    if (threadIdx.x == 0) {
        __threadfence();
        unsigned tk = atomicAdd(&g_barcnt, 1u);
        unsigned target = (tk / NCTA) * NCTA + NCTA;
        while ((int)(*(volatile unsigned*)&g_barcnt - target) < 0) {}
        __threadfence();
    }
    __syncthreads();
}

// ---------------- prep: fp32 -> bf16 hi/lo splits (x + 4 weights), biases ----
__global__ void prep_split(const float* __restrict__ x,
                           const float* __restrict__ w0, const float* __restrict__ w1,
                           const float* __restrict__ w2, const float* __restrict__ w3,
                           bf16* __restrict__ ahi, bf16* __restrict__ alo,
                           bf16* __restrict__ whi, bf16* __restrict__ wlo) {
    const size_t total = XLEN + 4ull * GH;
    for (size_t i = (size_t)blockIdx.x * blockDim.x + threadIdx.x; i < total;
         i += (size_t)gridDim.x * blockDim.x) {
        float v; bf16 *dh, *dl;
        if (i < XLEN) {
            v = x[i]; dh = ahi + i; dl = alo + i;
        } else {
            size_t j = i - XLEN;
            int w = (int)(j >> 22);
            size_t k = j & (GH - 1);
            const float* src = (w == 0) ? w0 : (w == 1) ? w1 : (w == 2) ? w2 : w3;
            v = src[k]; dh = whi + j; dl = wlo + j;
        }
        bf16 h = __float2bfloat16(v);
        *dh = h;
        *dl = __float2bfloat16(v - __bfloat162float(h));
    }
}
__global__ void prep_bias(const float* __restrict__ a0, const float* __restrict__ b0,
                          const float* __restrict__ a1, const float* __restrict__ b1,
                          float* __restrict__ o) {
    int i = blockIdx.x * blockDim.x + threadIdx.x;
    if (i < NGATE) o[i] = a0[i] + b0[i];
    else if (i < 2 * NGATE) o[i] = a1[i - NGATE] + b1[i - NGATE];
}

// ---------------- big GEMM: out[M,4096] = A[M,1024] @ W[4096,1024]^T + bias --
// CTA tile 64x64, BK=32, 256 thr, 2-stage cp.async, ONE sync/iter. grid=(n64,m512).
__global__ __launch_bounds__(256) void gemm_xw(
    const bf16* __restrict__ Ahi, const bf16* __restrict__ Alo,
    const bf16* __restrict__ Whi, const bf16* __restrict__ Wlo,
    const float* __restrict__ bias, float* __restrict__ out) {
    __shared__ __align__(16) unsigned char sraw[40960];   // 4 arrays x 2 stages x 5120B
    const uint32_t sb = sptr(sraw);

    const int tid = threadIdx.x, warp = tid >> 5, lane = tid & 31;
    const size_t n0 = (size_t)blockIdx.x * 64, m0 = (size_t)blockIdx.y * 64;
    const int lr = tid >> 2, lc = (tid & 3) * 8;

    const bf16* pAhi = Ahi + (m0 + lr) * HID + lc;
    const bf16* pAlo = Alo + (m0 + lr) * HID + lc;
    const bf16* pBhi = Whi + (n0 + lr) * HID + lc;
    const bf16* pBlo = Wlo + (n0 + lr) * HID + lc;
    const uint32_t stb = (uint32_t)((lr * 40 + lc) * 2);

    const int mB = (warp & 3) * 16, nB = (warp >> 2) * 32;
    const int lrow = lane & 15;
    const uint32_t lkb2 = (uint32_t)((lane >> 4) * 16);
    const uint32_t aHiB  = sb +         (uint32_t)((mB + lrow) * 80) + lkb2;
    const uint32_t aLoB  = aHiB + 10240;
    const uint32_t bHiB0 = sb + 20480 + (uint32_t)((nB + lrow) * 80) + lkb2;
    const uint32_t bHiB1 = sb + 20480 + (uint32_t)((nB + 16 + lrow) * 80) + lkb2;
    const uint32_t bLoB0 = bHiB0 + 10240;
    const uint32_t bLoB1 = bHiB1 + 10240;

    float acc[4][4];
#pragma unroll
    for (int i = 0; i < 4; ++i)
#pragma unroll
        for (int j = 0; j < 4; ++j) acc[i][j] = 0.f;

#define GEMM_ISSUE(it, s) do {                                   \
        cpa16(sb +         (s) * 5120 + stb, pAhi + (it) * 32);  \
        cpa16(sb + 10240 + (s) * 5120 + stb, pAlo + (it) * 32);  \
        cpa16(sb + 20480 + (s) * 5120 + stb, pBhi + (it) * 32);  \
        cpa16(sb + 30720 + (s) * 5120 + stb, pBlo + (it) * 32);  \
        CP_COMMIT(); } while (0)

    GEMM_ISSUE(0, 0);
    for (int it = 0; it < 32; ++it) {
        CP_WAIT0();
        __syncthreads();                    // all done computing it-1 -> buf free
        if (it < 31) GEMM_ISSUE(it + 1, (it + 1) & 1);
        const uint32_t so = (uint32_t)((it & 1) * 5120);
#pragma unroll
        for (int kk = 0; kk < 2; ++kk) {
            const uint32_t ko = so + kk * 32;
            uint32_t ah[4], al[4], bh0[4], bh1[4], bl0[4], bl1[4];
            ldsm4(ah, aHiB + ko);   ldsm4(al, aLoB + ko);
            ldsm4(bh0, bHiB0 + ko); ldsm4(bh1, bHiB1 + ko);
            ldsm4(bl0, bLoB0 + ko); ldsm4(bl1, bLoB1 + ko);
            mma_nt(acc[0], ah, bh0[0], bh0[2]); mma_nt(acc[0], ah, bl0[0], bl0[2]);
            mma_nt(acc[0], al, bh0[0], bh0[2]);
            mma_nt(acc[1], ah, bh0[1], bh0[3]); mma_nt(acc[1], ah, bl0[1], bl0[3]);
            mma_nt(acc[1], al, bh0[1], bh0[3]);
            mma_nt(acc[2], ah, bh1[0], bh1[2]); mma_nt(acc[2], ah, bl1[0], bl1[2]);
            mma_nt(acc[2], al, bh1[0], bh1[2]);
            mma_nt(acc[3], ah, bh1[1], bh1[3]); mma_nt(acc[3], ah, bl1[1], bl1[3]);
            mma_nt(acc[3], al, bh1[1], bh1[3]);
        }
    }
#undef GEMM_ISSUE
    __syncthreads();

    const size_t row0 = m0 + mB + (lane >> 2);
#pragma unroll
    for (int nb = 0; nb < 4; ++nb) {
        const size_t col = n0 + nB + nb * 8 + (lane & 3) * 2;
        const float b0 = bias[col], b1 = bias[col + 1];
        float2* o0 = (float2*)(out + row0 * NGATE + col);
        float2* o1 = (float2*)(out + (row0 + 8) * NGATE + col);
        *o0 = make_float2(acc[nb][0] + b0, acc[nb][1] + b1);
        *o1 = make_float2(acc[nb][2] + b0, acc[nb][3] + b1);
    }
}

// ---------------- persistent recurrent layer ---------------------------------
// 128 CTAs (all resident). CTA: 64 batch x 8 h-cols x 4 gates (N=32 tile).
// 3-stage cp.async (tile it -> stage it%3), one sync per k-iter.
// c state in registers; grid barrier between timesteps.
// smem: Ahi[3][5120] Alo[3][5120] Bhi[3][2560] Blo[3][2560] = 46080B; sG aliases.
__global__ __launch_bounds__(256) void lstm_layer(
    const bf16* __restrict__ Whi, const bf16* __restrict__ Wlo,   // whh splits
    const float* __restrict__ xw,                                 // [512][64][4096]
    bf16* __restrict__ hHi, bf16* __restrict__ hLo,               // slot t out / t-1 in
    float* __restrict__ outF) {                                   // null for layer 0
    __shared__ __align__(16) unsigned char sraw[46080];
    float* sG = (float*)sraw;                                     // 64*33*4 = 8448B
    const uint32_t sb = sptr(sraw);

    const int tid = threadIdx.x, warp = tid >> 5, lane = tid & 31;
    const int hs = blockIdx.x * 8;
    // A loaders: all 256 threads, 64 rows x 32 cols bf16 per stage
    const int lrA = tid >> 2, lcA = (tid & 3) * 8;
    const uint32_t stbA = (uint32_t)((lrA * 40 + lcA) * 2);
    // B loaders: threads 0-127 hi, 128-255 lo; 32 rows x 32 cols
    const int jj = (tid & 127) >> 2, cc = (tid & 3) * 8;
    const int wrow = (jj >> 3) * HID + hs + (jj & 7);             // gate*1024 + h-col
    const bf16* pB = ((tid < 128) ? Whi : Wlo) + (size_t)wrow * HID + cc;
    const uint32_t dstB = sb + ((tid < 128) ? 30720u : 38400u);
    const uint32_t stbB = (uint32_t)((jj * 40 + cc) * 2);

    const int mB = (warp & 3) * 16, nB = (warp >> 2) * 16;
    const int lrow = lane & 15;
    const uint32_t lkb2 = (uint32_t)((lane >> 4) * 16);
    const uint32_t aHiB = sb +         (uint32_t)((mB + lrow) * 80) + lkb2;
    const uint32_t aLoB = sb + 15360 + (uint32_t)((mB + lrow) * 80) + lkb2;
    const uint32_t bHiB = sb + 30720 + (uint32_t)((nB + lrow) * 80) + lkb2;
    const uint32_t bLoB = sb + 38400 + (uint32_t)((nB + lrow) * 80) + lkb2;

    float creg[2] = {0.f, 0.f};

#pragma unroll 1
    for (int t = 0; t < TSTEPS; ++t) {
        float acc[2][4];
#pragma unroll
        for (int i = 0; i < 2; ++i)
#pragma unroll
            for (int j = 0; j < 4; ++j) acc[i][j] = 0.f;

        if (t > 0) {
            const bf16* pAhi = hHi + (size_t)(t - 1) * NBATCH * HID + lrA * HID + lcA;
            const bf16* pAlo = hLo + (size_t)(t - 1) * NBATCH * HID + lrA * HID + lcA;
#define STEP_ISSUE(it, s) do {                                        \
            cpa16(sb +         (uint32_t)(s) * 5120 + stbA, pAhi + (it) * 32); \
            cpa16(sb + 15360 + (uint32_t)(s) * 5120 + stbA, pAlo + (it) * 32); \
            cpa16(dstB +       (uint32_t)(s) * 2560 + stbB, pB + (it) * 32);   \
            CP_COMMIT(); } while (0)
            STEP_ISSUE(0, 0);
            STEP_ISSUE(1, 1);
            int cstage = 0;                 // stage holding tile `it`   (= it%3)
            int istage = 2;                 // stage for tile `it+2`     (= (it+2)%3)
            for (int it = 0; it < 32; ++it) {
                if (it < 31) CP_WAIT1(); else CP_WAIT0();
                __syncthreads();            // readers of tile it-1 are done
                if (it + 2 < 32) STEP_ISSUE(it + 2, istage);
                const uint32_t so5 = (uint32_t)cstage * 5120;
                const uint32_t so2 = (uint32_t)cstage * 2560;
#pragma unroll
                for (int kk = 0; kk < 2; ++kk) {
                    const uint32_t ko = kk * 32;
                    uint32_t ah[4], al[4], bh[4], bl[4];
                    ldsm4(ah, aHiB + so5 + ko); ldsm4(al, aLoB + so5 + ko);
                    ldsm4(bh, bHiB + so2 + ko); ldsm4(bl, bLoB + so2 + ko);
                    mma_nt(acc[0], ah, bh[0], bh[2]); mma_nt(acc[0], ah, bl[0], bl[2]);
                    mma_nt(acc[0], al, bh[0], bh[2]);
                    mma_nt(acc[1], ah, bh[1], bh[3]); mma_nt(acc[1], ah, bl[1], bl[3]);
                    mma_nt(acc[1], al, bh[1], bh[3]);
                }
                cstage = cstage + 1 == 3 ? 0 : cstage + 1;
                istage = istage + 1 == 3 ? 0 : istage + 1;
            }
#undef STEP_ISSUE
        }
        __syncthreads();                    // pipeline buffers -> sG alias safe

        // stage recurrent gate sums (local col j in 0..31 = gate*8 + hcol)
        {
            const int row0 = mB + (lane >> 2);
#pragma unroll
            for (int nb = 0; nb < 2; ++nb) {
                const int j = nB + nb * 8 + (lane & 3) * 2;
                sG[row0 * 33 + j]           = acc[nb][0];
                sG[row0 * 33 + j + 1]       = acc[nb][1];
                sG[(row0 + 8) * 33 + j]     = acc[nb][2];
                sG[(row0 + 8) * 33 + j + 1] = acc[nb][3];
            }
        }
        __syncthreads();

        // epilogue: 64 batch x 8 h-cols = 512 elements; c in registers
        const float* xwt = xw + (size_t)t * NBATCH * NGATE;
        const size_t obase = (size_t)t * NBATCH * HID;
#pragma unroll
        for (int k2 = 0; k2 < 2; ++k2) {
            const int e = tid + k2 * 256;
            const int m = e >> 3, j = e & 7, hc = hs + j;
            const float* xwm = xwt + (size_t)m * NGATE;
            const float ii = sG[m * 33 + j]      + xwm[hc];
            const float ff = sG[m * 33 + 8 + j]  + xwm[HID + hc];
            const float gg = sG[m * 33 + 16 + j] + xwm[2 * HID + hc];
            const float oo = sG[m * 33 + 24 + j] + xwm[3 * HID + hc];
            const float c  = sigf(ff) * creg[k2] + sigf(ii) * tanhf(gg);
            const float h  = sigf(oo) * tanhf(c);
            creg[k2] = c;
            const bf16 hh = __float2bfloat16(h);
            const size_t oidx = obase + (size_t)m * HID + hc;
            hHi[oidx] = hh;
            hLo[oidx] = __float2bfloat16(h - __bfloat162float(hh));
            if (outF) outF[oidx] = h;
        }
        grid_barrier<128>();
    }
}

// ---------------- host ------------------------------------------------------
extern "C" void kernel_launch(void* const* d_in, const int* in_sizes, int n_in,
                              void* d_out, int out_size) {
    const float* x    = (const float*)d_in[0];
    const float* wih0 = (const float*)d_in[1];
    const float* whh0 = (const float*)d_in[2];
    const float* bih0 = (const float*)d_in[3];
    const float* bhh0 = (const float*)d_in[4];
    const float* wih1 = (const float*)d_in[5];
    const float* whh1 = (const float*)d_in[6];
    const float* bih1 = (const float*)d_in[7];
    const float* bhh1 = (const float*)d_in[8];

    float *xw, *bias;
    bf16 *ahi, *alo, *whi, *wlo;
    cudaGetSymbolAddress((void**)&xw,   g_xw);
    cudaGetSymbolAddress((void**)&ahi,  g_ahi);
    cudaGetSymbolAddress((void**)&alo,  g_alo);
    cudaGetSymbolAddress((void**)&whi,  g_whi);
    cudaGetSymbolAddress((void**)&wlo,  g_wlo);
    cudaGetSymbolAddress((void**)&bias, g_bias);

    // launch order fixed so ncu (-s 5 -c 1) profiles lstm_layer (layer 1)
    prep_split<<<4096, 256>>>(x, wih0, whh0, wih1, whh1, ahi, alo, whi, wlo);
    prep_bias<<<32, 256>>>(bih0, bhh0, bih1, bhh1, bias);

    for (int layer = 0; layer < 2; ++layer) {
        const size_t wih_off = (size_t)(2 * layer) * GH;
        const size_t whh_off = (size_t)(2 * layer + 1) * GH;
        gemm_xw<<<dim3(64, 512), 256>>>(ahi, alo, whi + wih_off, wlo + wih_off,
                                        bias + layer * NGATE, xw);
        lstm_layer<<<128, 256>>>(whi + whh_off, wlo + whh_off, xw, ahi, alo,
                                 layer ? (float*)d_out : nullptr);
    }
}

// round 10
// speedup vs baseline: 1.5783x; 1.0716x over previous
#include <cuda_runtime.h>
#include <cuda_bf16.h>
#include <cstdint>
#include <cstddef>

#define TSTEPS 512
#define NBATCH 64
#define HID    1024
#define NGATE  4096
#define TBROWS (TSTEPS * NBATCH)          // 32768
#define GH     (NGATE * HID)              // 4194304 = 2^22
#define XLEN   ((size_t)TBROWS * HID)     // 33554432

// lstm_layer dynamic smem layout (bytes):
//   A hi stages:  [0      , 15360)   3 x 5120
//   A lo stages:  [15360  , 30720)   3 x 5120
//   B hi tiles :  [30720  , 112640)  32 x 2560  (resident all steps)
//   B lo tiles :  [112640 , 194560)  32 x 2560
//   sG aliases A region (8448 B)
#define SM_ALO   15360u
#define SM_BHI   30720u
#define SM_BLO   112640u
#define SM_TOTAL 194560

typedef __nv_bfloat16 bf16;

// ---------------- static device scratch (no runtime allocation) -------------
__device__ float    g_xw[(size_t)TBROWS * NGATE];     // 536 MB, per-layer reuse
__device__ bf16     g_ahi[XLEN];                      // x splits -> h1 -> h2
__device__ bf16     g_alo[XLEN];
__device__ bf16     g_whi[4ull * GH];                 // wih0, whh0, wih1, whh1
__device__ bf16     g_wlo[4ull * GH];
__device__ float    g_bias[2 * NGATE];
__device__ unsigned g_barcnt;                         // monotonic grid barrier

// ---------------- helpers ---------------------------------------------------
static __device__ __forceinline__ uint32_t sptr(const void* p) {
    return (uint32_t)__cvta_generic_to_shared(p);
}
static __device__ __forceinline__ void ldsm4(uint32_t* r, uint32_t a) {
    asm volatile("ldmatrix.sync.aligned.m8n8.x4.shared.b16 {%0,%1,%2,%3}, [%4];\n"
                 : "=r"(r[0]), "=r"(r[1]), "=r"(r[2]), "=r"(r[3]) : "r"(a));
}
static __device__ __forceinline__ void mma_nt(float* d, const uint32_t* a,
                                              uint32_t b0, uint32_t b1) {
    asm volatile(
        "mma.sync.aligned.m16n8k16.row.col.f32.bf16.bf16.f32 "
        "{%0,%1,%2,%3},{%4,%5,%6,%7},{%8,%9},{%0,%1,%2,%3};\n"
        : "+f"(d[0]), "+f"(d[1]), "+f"(d[2]), "+f"(d[3])
        : "r"(a[0]), "r"(a[1]), "r"(a[2]), "r"(a[3]), "r"(b0), "r"(b1));
}
static __device__ __forceinline__ void cpa16(uint32_t dst, const void* src) {
    asm volatile("cp.async.cg.shared.global [%0], [%1], 16;\n" :: "r"(dst), "l"(src));
}
#define CP_COMMIT() asm volatile("cp.async.commit_group;\n")
#define CP_WAIT1()  asm volatile("cp.async.wait_group 1;\n")
#define CP_WAIT0()  asm volatile("cp.async.wait_group 0;\n")
static __device__ __forceinline__ float sigf(float x) { return 1.f / (1.f + expf(-x)); }

// Grid barrier over NCTA CTAs: monotonic ticket counter (graph-replay safe).
template <unsigned NCTA>
static __device__ __forceinline__ void grid_barrier() {
    __syncthreads();
    if (threadIdx.x == 0) {
        __threadfence();
        unsigned tk = atomicAdd(&g_barcnt, 1u);
        unsigned target = (tk / NCTA) * NCTA + NCTA;
        while ((int)(*(volatile unsigned*)&g_barcnt - target) < 0) {}
        __threadfence();
    }
    __syncthreads();
}

// ---------------- prep: fp32 -> bf16 hi/lo splits (x + 4 weights), biases ----
__global__ void prep_split(const float* __restrict__ x,
                           const float* __restrict__ w0, const float* __restrict__ w1,
                           const float* __restrict__ w2, const float* __restrict__ w3,
                           bf16* __restrict__ ahi, bf16* __restrict__ alo,
                           bf16* __restrict__ whi, bf16* __restrict__ wlo) {
    const size_t total = XLEN + 4ull * GH;
    for (size_t i = (size_t)blockIdx.x * blockDim.x + threadIdx.x; i < total;
         i += (size_t)gridDim.x * blockDim.x) {
        float v; bf16 *dh, *dl;
        if (i < XLEN) {
            v = x[i]; dh = ahi + i; dl = alo + i;
        } else {
            size_t j = i - XLEN;
            int w = (int)(j >> 22);
            size_t k = j & (GH - 1);
            const float* src = (w == 0) ? w0 : (w == 1) ? w1 : (w == 2) ? w2 : w3;
            v = src[k]; dh = whi + j; dl = wlo + j;
        }
        bf16 h = __float2bfloat16(v);
        *dh = h;
        *dl = __float2bfloat16(v - __bfloat162float(h));
    }
}
__global__ void prep_bias(const float* __restrict__ a0, const float* __restrict__ b0,
                          const float* __restrict__ a1, const float* __restrict__ b1,
                          float* __restrict__ o) {
    int i = blockIdx.x * blockDim.x + threadIdx.x;
    if (i < NGATE) o[i] = a0[i] + b0[i];
    else if (i < 2 * NGATE) o[i] = a1[i - NGATE] + b1[i - NGATE];
}

// ---------------- big GEMM: out[M,4096] = A[M,1024] @ W[4096,1024]^T + bias --
// CTA tile 64x64, BK=32, 256 thr, 2-stage cp.async, ONE sync/iter. grid=(n64,m512).
__global__ __launch_bounds__(256) void gemm_xw(
    const bf16* __restrict__ Ahi, const bf16* __restrict__ Alo,
    const bf16* __restrict__ Whi, const bf16* __restrict__ Wlo,
    const float* __restrict__ bias, float* __restrict__ out) {
    __shared__ __align__(16) unsigned char sraw[40960];   // 4 arrays x 2 stages x 5120B
    const uint32_t sb = sptr(sraw);

    const int tid = threadIdx.x, warp = tid >> 5, lane = tid & 31;
    const size_t n0 = (size_t)blockIdx.x * 64, m0 = (size_t)blockIdx.y * 64;
    const int lr = tid >> 2, lc = (tid & 3) * 8;

    const bf16* pAhi = Ahi + (m0 + lr) * HID + lc;
    const bf16* pAlo = Alo + (m0 + lr) * HID + lc;
    const bf16* pBhi = Whi + (n0 + lr) * HID + lc;
    const bf16* pBlo = Wlo + (n0 + lr) * HID + lc;
    const uint32_t stb = (uint32_t)((lr * 40 + lc) * 2);

    const int mB = (warp & 3) * 16, nB = (warp >> 2) * 32;
    const int lrow = lane & 15;
    const uint32_t lkb2 = (uint32_t)((lane >> 4) * 16);
    const uint32_t aHiB  = sb +         (uint32_t)((mB + lrow) * 80) + lkb2;
    const uint32_t aLoB  = aHiB + 10240;
    const uint32_t bHiB0 = sb + 20480 + (uint32_t)((nB + lrow) * 80) + lkb2;
    const uint32_t bHiB1 = sb + 20480 + (uint32_t)((nB + 16 + lrow) * 80) + lkb2;
    const uint32_t bLoB0 = bHiB0 + 10240;
    const uint32_t bLoB1 = bHiB1 + 10240;

    float acc[4][4];
#pragma unroll
    for (int i = 0; i < 4; ++i)
#pragma unroll
        for (int j = 0; j < 4; ++j) acc[i][j] = 0.f;

#define GEMM_ISSUE(it, s) do {                                   \
        cpa16(sb +         (s) * 5120 + stb, pAhi + (it) * 32);  \
        cpa16(sb + 10240 + (s) * 5120 + stb, pAlo + (it) * 32);  \
        cpa16(sb + 20480 + (s) * 5120 + stb, pBhi + (it) * 32);  \
        cpa16(sb + 30720 + (s) * 5120 + stb, pBlo + (it) * 32);  \
        CP_COMMIT(); } while (0)

    GEMM_ISSUE(0, 0);
    for (int it = 0; it < 32; ++it) {
        CP_WAIT0();
        __syncthreads();                    // all done computing it-1 -> buf free
        if (it < 31) GEMM_ISSUE(it + 1, (it + 1) & 1);
        const uint32_t so = (uint32_t)((it & 1) * 5120);
#pragma unroll
        for (int kk = 0; kk < 2; ++kk) {
            const uint32_t ko = so + kk * 32;
            uint32_t ah[4], al[4], bh0[4], bh1[4], bl0[4], bl1[4];
            ldsm4(ah, aHiB + ko);   ldsm4(al, aLoB + ko);
            ldsm4(bh0, bHiB0 + ko); ldsm4(bh1, bHiB1 + ko);
            ldsm4(bl0, bLoB0 + ko); ldsm4(bl1, bLoB1 + ko);
            mma_nt(acc[0], ah, bh0[0], bh0[2]); mma_nt(acc[0], ah, bl0[0], bl0[2]);
            mma_nt(acc[0], al, bh0[0], bh0[2]);
            mma_nt(acc[1], ah, bh0[1], bh0[3]); mma_nt(acc[1], ah, bl0[1], bl0[3]);
            mma_nt(acc[1], al, bh0[1], bh0[3]);
            mma_nt(acc[2], ah, bh1[0], bh1[2]); mma_nt(acc[2], ah, bl1[0], bl1[2]);
            mma_nt(acc[2], al, bh1[0], bh1[2]);
            mma_nt(acc[3], ah, bh1[1], bh1[3]); mma_nt(acc[3], ah, bl1[1], bl1[3]);
            mma_nt(acc[3], al, bh1[1], bh1[3]);
        }
    }
#undef GEMM_ISSUE
    __syncthreads();

    const size_t row0 = m0 + mB + (lane >> 2);
#pragma unroll
    for (int nb = 0; nb < 4; ++nb) {
        const size_t col = n0 + nB + nb * 8 + (lane & 3) * 2;
        const float b0 = bias[col], b1 = bias[col + 1];
        float2* o0 = (float2*)(out + row0 * NGATE + col);
        float2* o1 = (float2*)(out + (row0 + 8) * NGATE + col);
        *o0 = make_float2(acc[nb][0] + b0, acc[nb][1] + b1);
        *o1 = make_float2(acc[nb][2] + b0, acc[nb][3] + b1);
    }
}

// ---------------- persistent recurrent layer ---------------------------------
// 128 CTAs (all resident). CTA: 64 batch x 8 h-cols x 4 gates (N=32 tile).
// W_hh hi/lo (160 KB padded) loaded ONCE into dynamic SMEM, resident all steps.
// Per step only A (h splits) streams: 3-stage cp.async, tile it -> stage it%3,
// one sync per k-iter. c state in registers; grid barrier between timesteps.
__global__ __launch_bounds__(256) void lstm_layer(
    const bf16* __restrict__ Whi, const bf16* __restrict__ Wlo,   // whh splits
    const float* __restrict__ xw,                                 // [512][64][4096]
    bf16* __restrict__ hHi, bf16* __restrict__ hLo,               // slot t out / t-1 in
    float* __restrict__ outF) {                                   // null for layer 0
    extern __shared__ __align__(16) unsigned char sraw[];
    float* sG = (float*)sraw;                                     // 64*33*4 = 8448B
    const uint32_t sb = sptr(sraw);

    const int tid = threadIdx.x, warp = tid >> 5, lane = tid & 31;
    const int hs = blockIdx.x * 8;
    // A loaders: all 256 threads, 64 rows x 32 cols bf16 per stage
    const int lrA = tid >> 2, lcA = (tid & 3) * 8;
    const uint32_t stbA = (uint32_t)((lrA * 40 + lcA) * 2);
    // B loaders: threads 0-127 hi, 128-255 lo; 32 rows x 32 cols per k-tile
    const int jj = (tid & 127) >> 2, cc = (tid & 3) * 8;
    const int wrow = (jj >> 3) * HID + hs + (jj & 7);             // gate*1024 + h-col
    const bf16* pB = ((tid < 128) ? Whi : Wlo) + (size_t)wrow * HID + cc;
    const uint32_t dstB = sb + ((tid < 128) ? SM_BHI : SM_BLO);
    const uint32_t stbB = (uint32_t)((jj * 40 + cc) * 2);

    const int mB = (warp & 3) * 16, nB = (warp >> 2) * 16;
    const int lrow = lane & 15;
    const uint32_t lkb2 = (uint32_t)((lane >> 4) * 16);
    const uint32_t aHiB = sb +          (uint32_t)((mB + lrow) * 80) + lkb2;
    const uint32_t aLoB = sb + SM_ALO + (uint32_t)((mB + lrow) * 80) + lkb2;
    const uint32_t bHiB = sb + SM_BHI + (uint32_t)((nB + lrow) * 80) + lkb2;
    const uint32_t bLoB = sb + SM_BLO + (uint32_t)((nB + lrow) * 80) + lkb2;

    // ---- load W_hh tile (hi+lo, all 32 k-tiles) into SMEM once ----
#pragma unroll 4
    for (int it = 0; it < 32; ++it)
        cpa16(dstB + (uint32_t)it * 2560 + stbB, pB + it * 32);
    CP_COMMIT();
    CP_WAIT0();
    __syncthreads();

    // epilogue element mapping (per thread: 2 elements)
    const int em0 = tid >> 3,        ej0 = tid & 7;
    const int em1 = (tid + 256) >> 3, ej1 = (tid + 256) & 7;

    float creg[2] = {0.f, 0.f};

#pragma unroll 1
    for (int t = 0; t < TSTEPS; ++t) {
        // prefetch this step's xw gate biases into registers (hides L2 latency)
        const float* xwt = xw + (size_t)t * NBATCH * NGATE;
        const float* x0 = xwt + (size_t)em0 * NGATE + hs + ej0;
        const float* x1 = xwt + (size_t)em1 * NGATE + hs + ej1;
        float xr0i = x0[0], xr0f = x0[HID], xr0g = x0[2 * HID], xr0o = x0[3 * HID];
        float xr1i = x1[0], xr1f = x1[HID], xr1g = x1[2 * HID], xr1o = x1[3 * HID];

        float acc[2][4];
#pragma unroll
        for (int i = 0; i < 2; ++i)
#pragma unroll
            for (int j = 0; j < 4; ++j) acc[i][j] = 0.f;

        if (t > 0) {
            const bf16* pAhi = hHi + (size_t)(t - 1) * NBATCH * HID + lrA * HID + lcA;
            const bf16* pAlo = hLo + (size_t)(t - 1) * NBATCH * HID + lrA * HID + lcA;
#define STEP_ISSUE(it, s) do {                                                 \
            cpa16(sb +          (uint32_t)(s) * 5120 + stbA, pAhi + (it) * 32); \
            cpa16(sb + SM_ALO + (uint32_t)(s) * 5120 + stbA, pAlo + (it) * 32); \
            CP_COMMIT(); } while (0)
            STEP_ISSUE(0, 0);
            STEP_ISSUE(1, 1);
            int cstage = 0;                 // stage holding tile `it`   (= it%3)
            int istage = 2;                 // stage for tile `it+2`     (= (it+2)%3)
            for (int it = 0; it < 32; ++it) {
                if (it < 31) CP_WAIT1(); else CP_WAIT0();
                __syncthreads();            // readers of tile it-1 are done
                if (it + 2 < 32) STEP_ISSUE(it + 2, istage);
                const uint32_t so5 = (uint32_t)cstage * 5120;
                const uint32_t bof = (uint32_t)it * 2560;
#pragma unroll
                for (int kk = 0; kk < 2; ++kk) {
                    const uint32_t ko = kk * 32;
                    uint32_t ah[4], al[4], bh[4], bl[4];
                    ldsm4(ah, aHiB + so5 + ko); ldsm4(al, aLoB + so5 + ko);
                    ldsm4(bh, bHiB + bof + ko); ldsm4(bl, bLoB + bof + ko);
                    mma_nt(acc[0], ah, bh[0], bh[2]); mma_nt(acc[0], ah, bl[0], bl[2]);
                    mma_nt(acc[0], al, bh[0], bh[2]);
                    mma_nt(acc[1], ah, bh[1], bh[3]); mma_nt(acc[1], ah, bl[1], bl[3]);
                    mma_nt(acc[1], al, bh[1], bh[3]);
                }
                cstage = cstage + 1 == 3 ? 0 : cstage + 1;
                istage = istage + 1 == 3 ? 0 : istage + 1;
            }
#undef STEP_ISSUE
        }
        __syncthreads();                    // A stages -> sG alias safe

        // stage recurrent gate sums (local col j in 0..31 = gate*8 + hcol)
        {
            const int row0 = mB + (lane >> 2);
#pragma unroll
            for (int nb = 0; nb < 2; ++nb) {
                const int j = nB + nb * 8 + (lane & 3) * 2;
                sG[row0 * 33 + j]           = acc[nb][0];
                sG[row0 * 33 + j + 1]       = acc[nb][1];
                sG[(row0 + 8) * 33 + j]     = acc[nb][2];
                sG[(row0 + 8) * 33 + j + 1] = acc[nb][3];
            }
        }
        __syncthreads();

        // epilogue: 64 batch x 8 h-cols = 512 elements; c in registers
        const size_t obase = (size_t)t * NBATCH * HID;
        {
            const float ii = sG[em0 * 33 + ej0]      + xr0i;
            const float ff = sG[em0 * 33 + 8 + ej0]  + xr0f;
            const float gg = sG[em0 * 33 + 16 + ej0] + xr0g;
            const float oo = sG[em0 * 33 + 24 + ej0] + xr0o;
            const float c  = sigf(ff) * creg[0] + sigf(ii) * tanhf(gg);
            const float h  = sigf(oo) * tanhf(c);
            creg[0] = c;
            const bf16 hh = __float2bfloat16(h);
            const size_t oidx = obase + (size_t)em0 * HID + hs + ej0;
            hHi[oidx] = hh;
            hLo[oidx] = __float2bfloat16(h - __bfloat162float(hh));
            if (outF) outF[oidx] = h;
        }
        {
            const float ii = sG[em1 * 33 + ej1]      + xr1i;
            const float ff = sG[em1 * 33 + 8 + ej1]  + xr1f;
            const float gg = sG[em1 * 33 + 16 + ej1] + xr1g;
            const float oo = sG[em1 * 33 + 24 + ej1] + xr1o;
            const float c  = sigf(ff) * creg[1] + sigf(ii) * tanhf(gg);
            const float h  = sigf(oo) * tanhf(c);
            creg[1] = c;
            const bf16 hh = __float2bfloat16(h);
            const size_t oidx = obase + (size_t)em1 * HID + hs + ej1;
            hHi[oidx] = hh;
            hLo[oidx] = __float2bfloat16(h - __bfloat162float(hh));
            if (outF) outF[oidx] = h;
        }
        grid_barrier<128>();
    }
}

// ---------------- host ------------------------------------------------------
extern "C" void kernel_launch(void* const* d_in, const int* in_sizes, int n_in,
                              void* d_out, int out_size) {
    const float* x    = (const float*)d_in[0];
    const float* wih0 = (const float*)d_in[1];
    const float* whh0 = (const float*)d_in[2];
    const float* bih0 = (const float*)d_in[3];
    const float* bhh0 = (const float*)d_in[4];
    const float* wih1 = (const float*)d_in[5];
    const float* whh1 = (const float*)d_in[6];
    const float* bih1 = (const float*)d_in[7];
    const float* bhh1 = (const float*)d_in[8];

    float *xw, *bias;
    bf16 *ahi, *alo, *whi, *wlo;
    cudaGetSymbolAddress((void**)&xw,   g_xw);
    cudaGetSymbolAddress((void**)&ahi,  g_ahi);
    cudaGetSymbolAddress((void**)&alo,  g_alo);
    cudaGetSymbolAddress((void**)&whi,  g_whi);
    cudaGetSymbolAddress((void**)&wlo,  g_wlo);
    cudaGetSymbolAddress((void**)&bias, g_bias);

    cudaFuncSetAttribute(lstm_layer, cudaFuncAttributeMaxDynamicSharedMemorySize,
                         SM_TOTAL);

    // launch order fixed so ncu (-s 5 -c 1) profiles lstm_layer (layer 1)
    prep_split<<<4096, 256>>>(x, wih0, whh0, wih1, whh1, ahi, alo, whi, wlo);
    prep_bias<<<32, 256>>>(bih0, bhh0, bih1, bhh1, bias);

    for (int layer = 0; layer < 2; ++layer) {
        const size_t wih_off = (size_t)(2 * layer) * GH;
        const size_t whh_off = (size_t)(2 * layer + 1) * GH;
        gemm_xw<<<dim3(64, 512), 256>>>(ahi, alo, whi + wih_off, wlo + wih_off,
                                        bias + layer * NGATE, xw);
        lstm_layer<<<128, 256, SM_TOTAL>>>(whi + whh_off, wlo + whh_off, xw, ahi, alo,
                                           layer ? (float*)d_out : nullptr);
    }
}

// round 11
// speedup vs baseline: 1.8227x; 1.1549x over previous
#include <cuda_runtime.h>
#include <cuda_bf16.h>
#include <cstdint>
#include <cstddef>

#define TSTEPS 512
#define NBATCH 64
#define HID    1024
#define NGATE  4096
#define TBROWS (TSTEPS * NBATCH)          // 32768
#define GH     (NGATE * HID)              // 4194304 = 2^22
#define XLEN   ((size_t)TBROWS * HID)     // 33554432

typedef __nv_bfloat16 bf16;

// lstm_layer dynamic smem (bytes):
//   A chunks: [0, 65536)  = group(4) x stage(2) x part(hi/lo) x 4096  (64x64B rows, SW64)
//   B hi    : [65536, 147456)  32 tiles x 2560 (32 rows x 80B), resident
//   B lo    : [147456, 229376)
//   sGp (4x64x33 fp32 = 33792B) aliases the A region after the k-loop
#define A_G_STRIDE  16384u
#define A_ST_STRIDE 8192u
#define A_PART      4096u
#define SM_B_HI     65536u
#define SM_B_LO     147456u
#define SM_LSTM_TOTAL 229376
#define SWZ(x) ((x) ^ (((x) >> 3) & 0x30))

// ---------------- static device scratch (no runtime allocation) -------------
__device__ float    g_xw[(size_t)TBROWS * NGATE];     // 536 MB, per-layer reuse
__device__ bf16     g_ahi[XLEN];                      // x splits -> h1 -> h2
__device__ bf16     g_alo[XLEN];
__device__ bf16     g_whi[4ull * GH];                 // wih0, whh0, wih1, whh1
__device__ bf16     g_wlo[4ull * GH];
__device__ float    g_bias[2 * NGATE];
__device__ unsigned g_barcnt;                         // monotonic grid barrier

// ---------------- helpers ---------------------------------------------------
static __device__ __forceinline__ uint32_t sptr(const void* p) {
    return (uint32_t)__cvta_generic_to_shared(p);
}
static __device__ __forceinline__ void ldsm4(uint32_t* r, uint32_t a) {
    asm volatile("ldmatrix.sync.aligned.m8n8.x4.shared.b16 {%0,%1,%2,%3}, [%4];\n"
                 : "=r"(r[0]), "=r"(r[1]), "=r"(r[2]), "=r"(r[3]) : "r"(a));
}
static __device__ __forceinline__ void mma_nt(float* d, const uint32_t* a,
                                              uint32_t b0, uint32_t b1) {
    asm volatile(
        "mma.sync.aligned.m16n8k16.row.col.f32.bf16.bf16.f32 "
        "{%0,%1,%2,%3},{%4,%5,%6,%7},{%8,%9},{%0,%1,%2,%3};\n"
        : "+f"(d[0]), "+f"(d[1]), "+f"(d[2]), "+f"(d[3])
        : "r"(a[0]), "r"(a[1]), "r"(a[2]), "r"(a[3]), "r"(b0), "r"(b1));
}
static __device__ __forceinline__ void cpa16(uint32_t dst, const void* src) {
    asm volatile("cp.async.cg.shared.global [%0], [%1], 16;\n" :: "r"(dst), "l"(src));
}
#define CP_COMMIT() asm volatile("cp.async.commit_group;\n")
#define CP_WAIT0()  asm volatile("cp.async.wait_group 0;\n")
static __device__ __forceinline__ float sigf(float x) { return 1.f / (1.f + expf(-x)); }

// Grid barrier over NCTA CTAs: monotonic ticket counter (graph-replay safe).
template <unsigned NCTA>
static __device__ __forceinline__ void grid_barrier() {
    __syncthreads();
    if (threadIdx.x == 0) {
        __threadfence();
        unsigned tk = atomicAdd(&g_barcnt, 1u);
        unsigned target = (tk / NCTA) * NCTA + NCTA;
        while ((int)(*(volatile unsigned*)&g_barcnt - target) < 0) {}
        __threadfence();
    }
    __syncthreads();
}

// ---------------- prep: fp32 -> bf16 hi/lo splits (x + 4 weights), biases ----
__global__ void prep_split(const float* __restrict__ x,
                           const float* __restrict__ w0, const float* __restrict__ w1,
                           const float* __restrict__ w2, const float* __restrict__ w3,
                           bf16* __restrict__ ahi, bf16* __restrict__ alo,
                           bf16* __restrict__ whi, bf16* __restrict__ wlo) {
    const size_t total = XLEN + 4ull * GH;
    for (size_t i = (size_t)blockIdx.x * blockDim.x + threadIdx.x; i < total;
         i += (size_t)gridDim.x * blockDim.x) {
        float v; bf16 *dh, *dl;
        if (i < XLEN) {
            v = x[i]; dh = ahi + i; dl = alo + i;
        } else {
            size_t j = i - XLEN;
            int w = (int)(j >> 22);
            size_t k = j & (GH - 1);
            const float* src = (w == 0) ? w0 : (w == 1) ? w1 : (w == 2) ? w2 : w3;
            v = src[k]; dh = whi + j; dl = wlo + j;
        }
        bf16 h = __float2bfloat16(v);
        *dh = h;
        *dl = __float2bfloat16(v - __bfloat162float(h));
    }
}
__global__ void prep_bias(const float* __restrict__ a0, const float* __restrict__ b0,
                          const float* __restrict__ a1, const float* __restrict__ b1,
                          float* __restrict__ o) {
    int i = blockIdx.x * blockDim.x + threadIdx.x;
    if (i < NGATE) o[i] = a0[i] + b0[i];
    else if (i < 2 * NGATE) o[i] = a1[i - NGATE] + b1[i - NGATE];
}

// ---------------- big GEMM: out[M,4096] = A[M,1024] @ W[4096,1024]^T + bias --
// CTA tile 64x64, BK=32, 256 thr, 2-stage cp.async, ONE sync/iter. grid=(n64,m512).
__global__ __launch_bounds__(256) void gemm_xw(
    const bf16* __restrict__ Ahi, const bf16* __restrict__ Alo,
    const bf16* __restrict__ Whi, const bf16* __restrict__ Wlo,
    const float* __restrict__ bias, float* __restrict__ out) {
    __shared__ __align__(16) unsigned char sraw[40960];   // 4 arrays x 2 stages x 5120B
    const uint32_t sb = sptr(sraw);

    const int tid = threadIdx.x, warp = tid >> 5, lane = tid & 31;
    const size_t n0 = (size_t)blockIdx.x * 64, m0 = (size_t)blockIdx.y * 64;
    const int lr = tid >> 2, lc = (tid & 3) * 8;

    const bf16* pAhi = Ahi + (m0 + lr) * HID + lc;
    const bf16* pAlo = Alo + (m0 + lr) * HID + lc;
    const bf16* pBhi = Whi + (n0 + lr) * HID + lc;
    const bf16* pBlo = Wlo + (n0 + lr) * HID + lc;
    const uint32_t stb = (uint32_t)((lr * 40 + lc) * 2);

    const int mB = (warp & 3) * 16, nB = (warp >> 2) * 32;
    const int lrow = lane & 15;
    const uint32_t lkb2 = (uint32_t)((lane >> 4) * 16);
    const uint32_t aHiB  = sb +         (uint32_t)((mB + lrow) * 80) + lkb2;
    const uint32_t aLoB  = aHiB + 10240;
    const uint32_t bHiB0 = sb + 20480 + (uint32_t)((nB + lrow) * 80) + lkb2;
    const uint32_t bHiB1 = sb + 20480 + (uint32_t)((nB + 16 + lrow) * 80) + lkb2;
    const uint32_t bLoB0 = bHiB0 + 10240;
    const uint32_t bLoB1 = bHiB1 + 10240;

    float acc[4][4];
#pragma unroll
    for (int i = 0; i < 4; ++i)
#pragma unroll
        for (int j = 0; j < 4; ++j) acc[i][j] = 0.f;

#define GEMM_ISSUE(it, s) do {                                   \
        cpa16(sb +         (s) * 5120 + stb, pAhi + (it) * 32);  \
        cpa16(sb + 10240 + (s) * 5120 + stb, pAlo + (it) * 32);  \
        cpa16(sb + 20480 + (s) * 5120 + stb, pBhi + (it) * 32);  \
        cpa16(sb + 30720 + (s) * 5120 + stb, pBlo + (it) * 32);  \
        CP_COMMIT(); } while (0)

    GEMM_ISSUE(0, 0);
    for (int it = 0; it < 32; ++it) {
        CP_WAIT0();
        __syncthreads();                    // all done computing it-1 -> buf free
        if (it < 31) GEMM_ISSUE(it + 1, (it + 1) & 1);
        const uint32_t so = (uint32_t)((it & 1) * 5120);
#pragma unroll
        for (int kk = 0; kk < 2; ++kk) {
            const uint32_t ko = so + kk * 32;
            uint32_t ah[4], al[4], bh0[4], bh1[4], bl0[4], bl1[4];
            ldsm4(ah, aHiB + ko);   ldsm4(al, aLoB + ko);
            ldsm4(bh0, bHiB0 + ko); ldsm4(bh1, bHiB1 + ko);
            ldsm4(bl0, bLoB0 + ko); ldsm4(bl1, bLoB1 + ko);
            mma_nt(acc[0], ah, bh0[0], bh0[2]); mma_nt(acc[0], ah, bl0[0], bl0[2]);
            mma_nt(acc[0], al, bh0[0], bh0[2]);
            mma_nt(acc[1], ah, bh0[1], bh0[3]); mma_nt(acc[1], ah, bl0[1], bl0[3]);
            mma_nt(acc[1], al, bh0[1], bh0[3]);
            mma_nt(acc[2], ah, bh1[0], bh1[2]); mma_nt(acc[2], ah, bl1[0], bl1[2]);
            mma_nt(acc[2], al, bh1[0], bh1[2]);
            mma_nt(acc[3], ah, bh1[1], bh1[3]); mma_nt(acc[3], ah, bl1[1], bl1[3]);
            mma_nt(acc[3], al, bh1[1], bh1[3]);
        }
    }
#undef GEMM_ISSUE
    __syncthreads();

    const size_t row0 = m0 + mB + (lane >> 2);
#pragma unroll
    for (int nb = 0; nb < 4; ++nb) {
        const size_t col = n0 + nB + nb * 8 + (lane & 3) * 2;
        const float b0 = bias[col], b1 = bias[col + 1];
        float2* o0 = (float2*)(out + row0 * NGATE + col);
        float2* o1 = (float2*)(out + (row0 + 8) * NGATE + col);
        *o0 = make_float2(acc[nb][0] + b0, acc[nb][1] + b1);
        *o1 = make_float2(acc[nb][2] + b0, acc[nb][3] + b1);
    }
}

// ---------------- persistent recurrent layer ---------------------------------
// 128 CTAs. CTA: 64 batch x 8 h-cols x 4 gates (N=32), K=1024.
// 8 warps = 4 k-groups (8 k-tiles each) x 2 m-halves; warp MMA tile 32m x 32n.
// B (W_hh hi/lo) resident in SMEM; A (h splits) streamed per group, 2-stage,
// ONE syncthreads per round (8/step). 4 partial accs reduced via SMEM.
__global__ __launch_bounds__(256) void lstm_layer(
    const bf16* __restrict__ Whi, const bf16* __restrict__ Wlo,   // whh splits
    const float* __restrict__ xw,                                 // [512][64][4096]
    bf16* __restrict__ hHi, bf16* __restrict__ hLo,               // slot t out / t-1 in
    float* __restrict__ outF) {                                   // null for layer 0
    extern __shared__ __align__(16) unsigned char sraw[];
    float* sGp = (float*)sraw;                 // [4][64][33] fp32, aliases A region
    const uint32_t sb = sptr(sraw);

    const int tid = threadIdx.x, warp = tid >> 5, lane = tid & 31;
    const int hs = blockIdx.x * 8;
    const int kg = warp >> 1;                  // k-group 0..3 (k-tiles 8kg..8kg+7)
    const int mhalf = warp & 1;                // rows mhalf*32 .. +31

    // ---- one-time resident B load (threads 0-127 hi, 128-255 lo) ----
    {
        const int jj = (tid & 127) >> 2, cc = (tid & 3) * 8;
        const int wrow = (jj >> 3) * HID + hs + (jj & 7);     // gate*1024 + h-col
        const bf16* pB = ((tid < 128) ? Whi : Wlo) + (size_t)wrow * HID + cc;
        const uint32_t dstB = sb + ((tid < 128) ? SM_B_HI : SM_B_LO)
                            + (uint32_t)((jj * 40 + cc) * 2);
#pragma unroll 4
        for (int it = 0; it < 32; ++it)
            cpa16(dstB + (uint32_t)it * 2560, pB + it * 32);
        CP_COMMIT();
        CP_WAIT0();
        __syncthreads();
    }

    // ---- A loader mapping: each thread owns one 16B granule per (group, part)
    const int arow = tid >> 2, acb = tid & 3;                 // 64 rows x 4 colblocks
    const size_t asrc = (size_t)arow * HID + acb * 8;
    const uint32_t adst = SWZ((uint32_t)(arow * 64 + acb * 16));

    // ---- ldsm bases ----
    const uint32_t aGbase = sb + (uint32_t)kg * A_G_STRIDE;
    const uint32_t a_row0 = (uint32_t)((mhalf * 32 + (lane & 15)) * 64);
    const uint32_t a_row1 = a_row0 + 16 * 64;
    const uint32_t ac16   = (uint32_t)((lane >> 4) * 16);     // + kk*32
    const uint32_t b_r0 = (uint32_t)((lane & 15) * 80) + ac16;
    const uint32_t b_r1 = b_r0 + 16 * 80;

    // epilogue element mapping (2 per thread)
    const int em0 = tid >> 3,         ej0 = tid & 7;
    const int em1 = (tid + 256) >> 3, ej1 = (tid + 256) & 7;

    float creg[2] = {0.f, 0.f};

#pragma unroll 1
    for (int t = 0; t < TSTEPS; ++t) {
        // prefetch this step's xw gate sums into registers
        const float* xwt = xw + (size_t)t * NBATCH * NGATE;
        const float* x0 = xwt + (size_t)em0 * NGATE + hs + ej0;
        const float* x1 = xwt + (size_t)em1 * NGATE + hs + ej1;
        float xr0i = x0[0], xr0f = x0[HID], xr0g = x0[2 * HID], xr0o = x0[3 * HID];
        float xr1i = x1[0], xr1f = x1[HID], xr1g = x1[2 * HID], xr1o = x1[3 * HID];

        float acc[2][4][4];
#pragma unroll
        for (int a = 0; a < 2; ++a)
#pragma unroll
            for (int b = 0; b < 4; ++b)
#pragma unroll
                for (int q = 0; q < 4; ++q) acc[a][b][q] = 0.f;

        if (t > 0) {
            const bf16* pAh = hHi + (size_t)(t - 1) * NBATCH * HID + asrc;
            const bf16* pAl = hLo + (size_t)(t - 1) * NBATCH * HID + asrc;
#define STEP_ISSUE(r, s) do {                                                  \
    _Pragma("unroll")                                                          \
    for (int g2 = 0; g2 < 4; ++g2) {                                           \
        const uint32_t d0 = sb + (uint32_t)g2 * A_G_STRIDE +                   \
                            (uint32_t)(s) * A_ST_STRIDE + adst;                \
        const int ko = (8 * g2 + (r)) * 32;                                    \
        cpa16(d0,          pAh + ko);                                          \
        cpa16(d0 + A_PART, pAl + ko);                                          \
    }                                                                          \
    CP_COMMIT(); } while (0)

            STEP_ISSUE(0, 0);
            for (int r = 0; r < 8; ++r) {
                CP_WAIT0();
                __syncthreads();             // readers of round r-1 done
                if (r < 7) STEP_ISSUE(r + 1, (r + 1) & 1);
                const uint32_t ab = aGbase + (uint32_t)(r & 1) * A_ST_STRIDE;
                const uint32_t bt = (uint32_t)((8 * kg + r) * 2560);
#pragma unroll
                for (int kk = 0; kk < 2; ++kk) {
                    const uint32_t ca = ac16 + (uint32_t)kk * 32;
                    const uint32_t kb = (uint32_t)kk * 32;
                    uint32_t ah0[4], ah1[4], al0[4], al1[4];
                    ldsm4(ah0, ab + SWZ(a_row0 + ca));
                    ldsm4(ah1, ab + SWZ(a_row1 + ca));
                    ldsm4(al0, ab + A_PART + SWZ(a_row0 + ca));
                    ldsm4(al1, ab + A_PART + SWZ(a_row1 + ca));
                    uint32_t bhA[4], bhB[4], blA[4], blB[4];
                    ldsm4(bhA, sb + SM_B_HI + bt + b_r0 + kb);
                    ldsm4(bhB, sb + SM_B_HI + bt + b_r1 + kb);
                    ldsm4(blA, sb + SM_B_LO + bt + b_r0 + kb);
                    ldsm4(blB, sb + SM_B_LO + bt + b_r1 + kb);
                    // m-half block 0 (rows mhalf*32 + 0..15)
                    mma_nt(acc[0][0], ah0, bhA[0], bhA[2]);
                    mma_nt(acc[0][0], ah0, blA[0], blA[2]);
                    mma_nt(acc[0][0], al0, bhA[0], bhA[2]);
                    mma_nt(acc[0][1], ah0, bhA[1], bhA[3]);
                    mma_nt(acc[0][1], ah0, blA[1], blA[3]);
                    mma_nt(acc[0][1], al0, bhA[1], bhA[3]);
                    mma_nt(acc[0][2], ah0, bhB[0], bhB[2]);
                    mma_nt(acc[0][2], ah0, blB[0], blB[2]);
                    mma_nt(acc[0][2], al0, bhB[0], bhB[2]);
                    mma_nt(acc[0][3], ah0, bhB[1], bhB[3]);
                    mma_nt(acc[0][3], ah0, blB[1], blB[3]);
                    mma_nt(acc[0][3], al0, bhB[1], bhB[3]);
                    // m-half block 1 (rows mhalf*32 + 16..31)
                    mma_nt(acc[1][0], ah1, bhA[0], bhA[2]);
                    mma_nt(acc[1][0], ah1, blA[0], blA[2]);
                    mma_nt(acc[1][0], al1, bhA[0], bhA[2]);
                    mma_nt(acc[1][1], ah1, bhA[1], bhA[3]);
                    mma_nt(acc[1][1], ah1, blA[1], blA[3]);
                    mma_nt(acc[1][1], al1, bhA[1], bhA[3]);
                    mma_nt(acc[1][2], ah1, bhB[0], bhB[2]);
                    mma_nt(acc[1][2], ah1, blB[0], blB[2]);
                    mma_nt(acc[1][2], al1, bhB[0], bhB[2]);
                    mma_nt(acc[1][3], ah1, bhB[1], bhB[3]);
                    mma_nt(acc[1][3], ah1, blB[1], blB[3]);
                    mma_nt(acc[1][3], al1, bhB[1], bhB[3]);
                }
            }
#undef STEP_ISSUE
        }
        __syncthreads();                     // A region free -> sGp alias safe

        // write split-K partials: sGp[kg][row][col], col = gate*8 + hcol
        {
            const int r0 = mhalf * 32 + (lane >> 2);
            const int c0 = (lane & 3) * 2;
#pragma unroll
            for (int mb = 0; mb < 2; ++mb) {
                const int base = kg * 2112 + (r0 + mb * 16) * 33 + c0;
#pragma unroll
                for (int nb = 0; nb < 4; ++nb) {
                    const int idx = base + nb * 8;
                    sGp[idx]            = acc[mb][nb][0];
                    sGp[idx + 1]        = acc[mb][nb][1];
                    sGp[idx + 8 * 33]     = acc[mb][nb][2];
                    sGp[idx + 8 * 33 + 1] = acc[mb][nb][3];
                }
            }
        }
        __syncthreads();

        // epilogue: 64 batch x 8 h-cols = 512 elements; sum 4 k-group partials
        const size_t obase = (size_t)t * NBATCH * HID;
        {
            const int i0 = em0 * 33 + ej0;
            const float ii = sGp[i0] + sGp[i0 + 2112] + sGp[i0 + 4224] + sGp[i0 + 6336] + xr0i;
            const int i1 = i0 + 8;
            const float ff = sGp[i1] + sGp[i1 + 2112] + sGp[i1 + 4224] + sGp[i1 + 6336] + xr0f;
            const int i2 = i0 + 16;
            const float gg = sGp[i2] + sGp[i2 + 2112] + sGp[i2 + 4224] + sGp[i2 + 6336] + xr0g;
            const int i3 = i0 + 24;
            const float oo = sGp[i3] + sGp[i3 + 2112] + sGp[i3 + 4224] + sGp[i3 + 6336] + xr0o;
            const float c = sigf(ff) * creg[0] + sigf(ii) * tanhf(gg);
            const float h = sigf(oo) * tanhf(c);
            creg[0] = c;
            const bf16 hh = __float2bfloat16(h);
            const size_t oidx = obase + (size_t)em0 * HID + hs + ej0;
            hHi[oidx] = hh;
            hLo[oidx] = __float2bfloat16(h - __bfloat162float(hh));
            if (outF) outF[oidx] = h;
        }
        {
            const int i0 = em1 * 33 + ej1;
            const float ii = sGp[i0] + sGp[i0 + 2112] + sGp[i0 + 4224] + sGp[i0 + 6336] + xr1i;
            const int i1 = i0 + 8;
            const float ff = sGp[i1] + sGp[i1 + 2112] + sGp[i1 + 4224] + sGp[i1 + 6336] + xr1f;
            const int i2 = i0 + 16;
            const float gg = sGp[i2] + sGp[i2 + 2112] + sGp[i2 + 4224] + sGp[i2 + 6336] + xr1g;
            const int i3 = i0 + 24;
            const float oo = sGp[i3] + sGp[i3 + 2112] + sGp[i3 + 4224] + sGp[i3 + 6336] + xr1o;
            const float c = sigf(ff) * creg[1] + sigf(ii) * tanhf(gg);
            const float h = sigf(oo) * tanhf(c);
            creg[1] = c;
            const bf16 hh = __float2bfloat16(h);
            const size_t oidx = obase + (size_t)em1 * HID + hs + ej1;
            hHi[oidx] = hh;
            hLo[oidx] = __float2bfloat16(h - __bfloat162float(hh));
            if (outF) outF[oidx] = h;
        }
        grid_barrier<128>();
    }
}

// ---------------- host ------------------------------------------------------
extern "C" void kernel_launch(void* const* d_in, const int* in_sizes, int n_in,
                              void* d_out, int out_size) {
    const float* x    = (const float*)d_in[0];
    const float* wih0 = (const float*)d_in[1];
    const float* whh0 = (const float*)d_in[2];
    const float* bih0 = (const float*)d_in[3];
    const float* bhh0 = (const float*)d_in[4];
    const float* wih1 = (const float*)d_in[5];
    const float* whh1 = (const float*)d_in[6];
    const float* bih1 = (const float*)d_in[7];
    const float* bhh1 = (const float*)d_in[8];

    float *xw, *bias;
    bf16 *ahi, *alo, *whi, *wlo;
    cudaGetSymbolAddress((void**)&xw,   g_xw);
    cudaGetSymbolAddress((void**)&ahi,  g_ahi);
    cudaGetSymbolAddress((void**)&alo,  g_alo);
    cudaGetSymbolAddress((void**)&whi,  g_whi);
    cudaGetSymbolAddress((void**)&wlo,  g_wlo);
    cudaGetSymbolAddress((void**)&bias, g_bias);

    cudaFuncSetAttribute(lstm_layer, cudaFuncAttributeMaxDynamicSharedMemorySize,
                         SM_LSTM_TOTAL);

    // launch order fixed so ncu (-s 5 -c 1) profiles lstm_layer (layer 1)
    prep_split<<<4096, 256>>>(x, wih0, whh0, wih1, whh1, ahi, alo, whi, wlo);
    prep_bias<<<32, 256>>>(bih0, bhh0, bih1, bhh1, bias);

    for (int layer = 0; layer < 2; ++layer) {
        const size_t wih_off = (size_t)(2 * layer) * GH;
        const size_t whh_off = (size_t)(2 * layer + 1) * GH;
        gemm_xw<<<dim3(64, 512), 256>>>(ahi, alo, whi + wih_off, wlo + wih_off,
                                        bias + layer * NGATE, xw);
        lstm_layer<<<128, 256, SM_LSTM_TOTAL>>>(whi + whh_off, wlo + whh_off, xw,
                                                ahi, alo,
                                                layer ? (float*)d_out : nullptr);
    }
}

// round 12
// speedup vs baseline: 1.9217x; 1.0543x over previous
#include <cuda_runtime.h>
#include <cuda_bf16.h>
#include <cstdint>
#include <cstddef>

#define TSTEPS 512
#define NBATCH 64
#define HID    1024
#define NGATE  4096
#define TBROWS (TSTEPS * NBATCH)          // 32768
#define GH     (NGATE * HID)              // 4194304 = 2^22
#define XLEN   ((size_t)TBROWS * HID)     // 33554432

typedef __nv_bfloat16 bf16;

// lstm_layer dynamic smem (bytes):
//   A chunks: [0, 98304)  = group(4) x stage(3) x part(hi/lo) x 4096 (64x64B, SWZ)
//   B hi    : [98304 , 163840)  32 tiles x 2048 (32x64B rows, SWZ), resident
//   B lo    : [163840, 229376)
//   sGp (4x64x33 fp32 = 33792B) aliases the A region after the k-loop
#define A_G_STRIDE  24576u
#define A_ST_STRIDE 8192u
#define A_PART      4096u
#define SM_B_HI     98304u
#define SM_B_LO     163840u
#define SM_LSTM_TOTAL 229376
#define SWZ(x) ((x) ^ (((x) >> 3) & 0x30))

// ---------------- static device scratch (no runtime allocation) -------------
__device__ float    g_xw[(size_t)TBROWS * NGATE];     // 536 MB, per-layer reuse
__device__ bf16     g_ahi[XLEN];                      // x splits -> h1 -> h2
__device__ bf16     g_alo[XLEN];
__device__ bf16     g_whi[4ull * GH];                 // wih0, whh0, wih1, whh1
__device__ bf16     g_wlo[4ull * GH];
__device__ float    g_bias[2 * NGATE];
__device__ unsigned g_barcnt;                         // monotonic grid barrier

// ---------------- helpers ---------------------------------------------------
static __device__ __forceinline__ uint32_t sptr(const void* p) {
    return (uint32_t)__cvta_generic_to_shared(p);
}
static __device__ __forceinline__ void ldsm4(uint32_t* r, uint32_t a) {
    asm volatile("ldmatrix.sync.aligned.m8n8.x4.shared.b16 {%0,%1,%2,%3}, [%4];\n"
                 : "=r"(r[0]), "=r"(r[1]), "=r"(r[2]), "=r"(r[3]) : "r"(a));
}
static __device__ __forceinline__ void mma_nt(float* d, const uint32_t* a,
                                              uint32_t b0, uint32_t b1) {
    asm volatile(
        "mma.sync.aligned.m16n8k16.row.col.f32.bf16.bf16.f32 "
        "{%0,%1,%2,%3},{%4,%5,%6,%7},{%8,%9},{%0,%1,%2,%3};\n"
        : "+f"(d[0]), "+f"(d[1]), "+f"(d[2]), "+f"(d[3])
        : "r"(a[0]), "r"(a[1]), "r"(a[2]), "r"(a[3]), "r"(b0), "r"(b1));
}
static __device__ __forceinline__ void cpa16(uint32_t dst, const void* src) {
    asm volatile("cp.async.cg.shared.global [%0], [%1], 16;\n" :: "r"(dst), "l"(src));
}
#define CP_COMMIT() asm volatile("cp.async.commit_group;\n")
#define CP_WAIT1()  asm volatile("cp.async.wait_group 1;\n")
#define CP_WAIT0()  asm volatile("cp.async.wait_group 0;\n")

// fast activations via MUFU ex2 path (~2 ulp): error ~1e-6, far under budget
static __device__ __forceinline__ float sigf(float x) {
    return __fdividef(1.f, 1.f + __expf(-x));
}
static __device__ __forceinline__ float tanhf_fast(float x) {
    float e = __expf(-2.f * fabsf(x));
    float t = __fdividef(1.f - e, 1.f + e);
    return copysignf(t, x);
}

// Grid barrier over NCTA CTAs: monotonic ticket counter (graph-replay safe).
template <unsigned NCTA>
static __device__ __forceinline__ void grid_barrier() {
    __syncthreads();
    if (threadIdx.x == 0) {
        __threadfence();
        unsigned tk = atomicAdd(&g_barcnt, 1u);
        unsigned target = (tk / NCTA) * NCTA + NCTA;
        while ((int)(*(volatile unsigned*)&g_barcnt - target) < 0) {}
        __threadfence();
    }
    __syncthreads();
}

// ---------------- prep: fp32 -> bf16 hi/lo splits (x + 4 weights), biases ----
__global__ void prep_split(const float* __restrict__ x,
                           const float* __restrict__ w0, const float* __restrict__ w1,
                           const float* __restrict__ w2, const float* __restrict__ w3,
                           bf16* __restrict__ ahi, bf16* __restrict__ alo,
                           bf16* __restrict__ whi, bf16* __restrict__ wlo) {
    const size_t total = XLEN + 4ull * GH;
    for (size_t i = (size_t)blockIdx.x * blockDim.x + threadIdx.x; i < total;
         i += (size_t)gridDim.x * blockDim.x) {
        float v; bf16 *dh, *dl;
        if (i < XLEN) {
            v = x[i]; dh = ahi + i; dl = alo + i;
        } else {
            size_t j = i - XLEN;
            int w = (int)(j >> 22);
            size_t k = j & (GH - 1);
            const float* src = (w == 0) ? w0 : (w == 1) ? w1 : (w == 2) ? w2 : w3;
            v = src[k]; dh = whi + j; dl = wlo + j;
        }
        bf16 h = __float2bfloat16(v);
        *dh = h;
        *dl = __float2bfloat16(v - __bfloat162float(h));
    }
}
__global__ void prep_bias(const float* __restrict__ a0, const float* __restrict__ b0,
                          const float* __restrict__ a1, const float* __restrict__ b1,
                          float* __restrict__ o) {
    int i = blockIdx.x * blockDim.x + threadIdx.x;
    if (i < NGATE) o[i] = a0[i] + b0[i];
    else if (i < 2 * NGATE) o[i] = a1[i - NGATE] + b1[i - NGATE];
}

// ---------------- big GEMM: out[M,4096] = A[M,1024] @ W[4096,1024]^T + bias --
// CTA tile 64x64, BK=32, 256 thr, 2-stage cp.async, ONE sync/iter. grid=(n64,m512).
__global__ __launch_bounds__(256) void gemm_xw(
    const bf16* __restrict__ Ahi, const bf16* __restrict__ Alo,
    const bf16* __restrict__ Whi, const bf16* __restrict__ Wlo,
    const float* __restrict__ bias, float* __restrict__ out) {
    __shared__ __align__(16) unsigned char sraw[40960];   // 4 arrays x 2 stages x 5120B
    const uint32_t sb = sptr(sraw);

    const int tid = threadIdx.x, warp = tid >> 5, lane = tid & 31;
    const size_t n0 = (size_t)blockIdx.x * 64, m0 = (size_t)blockIdx.y * 64;
    const int lr = tid >> 2, lc = (tid & 3) * 8;

    const bf16* pAhi = Ahi + (m0 + lr) * HID + lc;
    const bf16* pAlo = Alo + (m0 + lr) * HID + lc;
    const bf16* pBhi = Whi + (n0 + lr) * HID + lc;
    const bf16* pBlo = Wlo + (n0 + lr) * HID + lc;
    const uint32_t stb = (uint32_t)((lr * 40 + lc) * 2);

    const int mB = (warp & 3) * 16, nB = (warp >> 2) * 32;
    const int lrow = lane & 15;
    const uint32_t lkb2 = (uint32_t)((lane >> 4) * 16);
    const uint32_t aHiB  = sb +         (uint32_t)((mB + lrow) * 80) + lkb2;
    const uint32_t aLoB  = aHiB + 10240;
    const uint32_t bHiB0 = sb + 20480 + (uint32_t)((nB + lrow) * 80) + lkb2;
    const uint32_t bHiB1 = sb + 20480 + (uint32_t)((nB + 16 + lrow) * 80) + lkb2;
    const uint32_t bLoB0 = bHiB0 + 10240;
    const uint32_t bLoB1 = bHiB1 + 10240;

    float acc[4][4];
#pragma unroll
    for (int i = 0; i < 4; ++i)
#pragma unroll
        for (int j = 0; j < 4; ++j) acc[i][j] = 0.f;

#define GEMM_ISSUE(it, s) do {                                   \
        cpa16(sb +         (s) * 5120 + stb, pAhi + (it) * 32);  \
        cpa16(sb + 10240 + (s) * 5120 + stb, pAlo + (it) * 32);  \
        cpa16(sb + 20480 + (s) * 5120 + stb, pBhi + (it) * 32);  \
        cpa16(sb + 30720 + (s) * 5120 + stb, pBlo + (it) * 32);  \
        CP_COMMIT(); } while (0)

    GEMM_ISSUE(0, 0);
    for (int it = 0; it < 32; ++it) {
        CP_WAIT0();
        __syncthreads();                    // all done computing it-1 -> buf free
        if (it < 31) GEMM_ISSUE(it + 1, (it + 1) & 1);
        const uint32_t so = (uint32_t)((it & 1) * 5120);
#pragma unroll
        for (int kk = 0; kk < 2; ++kk) {
            const uint32_t ko = so + kk * 32;
            uint32_t ah[4], al[4], bh0[4], bh1[4], bl0[4], bl1[4];
            ldsm4(ah, aHiB + ko);   ldsm4(al, aLoB + ko);
            ldsm4(bh0, bHiB0 + ko); ldsm4(bh1, bHiB1 + ko);
            ldsm4(bl0, bLoB0 + ko); ldsm4(bl1, bLoB1 + ko);
            mma_nt(acc[0], ah, bh0[0], bh0[2]); mma_nt(acc[0], ah, bl0[0], bl0[2]);
            mma_nt(acc[0], al, bh0[0], bh0[2]);
            mma_nt(acc[1], ah, bh0[1], bh0[3]); mma_nt(acc[1], ah, bl0[1], bl0[3]);
            mma_nt(acc[1], al, bh0[1], bh0[3]);
            mma_nt(acc[2], ah, bh1[0], bh1[2]); mma_nt(acc[2], ah, bl1[0], bl1[2]);
            mma_nt(acc[2], al, bh1[0], bh1[2]);
            mma_nt(acc[3], ah, bh1[1], bh1[3]); mma_nt(acc[3], ah, bl1[1], bl1[3]);
            mma_nt(acc[3], al, bh1[1], bh1[3]);
        }
    }
#undef GEMM_ISSUE
    __syncthreads();

    const size_t row0 = m0 + mB + (lane >> 2);
#pragma unroll
    for (int nb = 0; nb < 4; ++nb) {
        const size_t col = n0 + nB + nb * 8 + (lane & 3) * 2;
        const float b0 = bias[col], b1 = bias[col + 1];
        float2* o0 = (float2*)(out + row0 * NGATE + col);
        float2* o1 = (float2*)(out + (row0 + 8) * NGATE + col);
        *o0 = make_float2(acc[nb][0] + b0, acc[nb][1] + b1);
        *o1 = make_float2(acc[nb][2] + b0, acc[nb][3] + b1);
    }
}

// ---------------- persistent recurrent layer ---------------------------------
// 128 CTAs. CTA: 64 batch x 8 h-cols x 4 gates (N=32), K=1024.
// 8 warps = 4 k-groups (8 k-tiles each) x 2 m-halves; warp MMA tile 32m x 32n.
// B (W_hh hi/lo) resident in SMEM (SWZ 64B rows); A streamed per group,
// 3-stage cp.async (prefetch distance 2 rounds), ONE syncthreads per round.
__global__ __launch_bounds__(256) void lstm_layer(
    const bf16* __restrict__ Whi, const bf16* __restrict__ Wlo,   // whh splits
    const float* __restrict__ xw,                                 // [512][64][4096]
    bf16* __restrict__ hHi, bf16* __restrict__ hLo,               // slot t out / t-1 in
    float* __restrict__ outF) {                                   // null for layer 0
    extern __shared__ __align__(16) unsigned char sraw[];
    float* sGp = (float*)sraw;                 // [4][64][33] fp32, aliases A region
    const uint32_t sb = sptr(sraw);

    const int tid = threadIdx.x, warp = tid >> 5, lane = tid & 31;
    const int hs = blockIdx.x * 8;
    const int kg = warp >> 1;                  // k-group 0..3 (k-tiles 8kg..8kg+7)
    const int mhalf = warp & 1;                // rows mhalf*32 .. +31

    // ---- one-time resident B load (threads 0-127 hi, 128-255 lo) ----
    {
        const int jj = (tid & 127) >> 2, cb = tid & 3;
        const int wrow = (jj >> 3) * HID + hs + (jj & 7);     // gate*1024 + h-col
        const bf16* pB = ((tid < 128) ? Whi : Wlo) + (size_t)wrow * HID + cb * 8;
        const uint32_t dstB = sb + ((tid < 128) ? SM_B_HI : SM_B_LO)
                            + SWZ((uint32_t)(jj * 64 + cb * 16));
#pragma unroll 4
        for (int it = 0; it < 32; ++it)
            cpa16(dstB + (uint32_t)it * 2048, pB + it * 32);
        CP_COMMIT();
        CP_WAIT0();
        __syncthreads();
    }

    // ---- A loader mapping: each thread owns one 16B granule per (group, part)
    const int arow = tid >> 2, acb = tid & 3;                 // 64 rows x 4 colblocks
    const size_t asrc = (size_t)arow * HID + acb * 8;
    const uint32_t adst = SWZ((uint32_t)(arow * 64 + acb * 16));

    // ---- ldsm bases (logical offsets; SWZ applied at use) ----
    const uint32_t aGbase = sb + (uint32_t)kg * A_G_STRIDE;
    const uint32_t a_row0 = (uint32_t)((mhalf * 32 + (lane & 15)) * 64);
    const uint32_t a_row1 = a_row0 + 16 * 64;
    const uint32_t ac16   = (uint32_t)((lane >> 4) * 16);     // + kk*32
    const uint32_t b_row0 = (uint32_t)((lane & 15) * 64);
    const uint32_t b_row1 = b_row0 + 16 * 64;

    // epilogue element mapping (2 per thread)
    const int em0 = tid >> 3,         ej0 = tid & 7;
    const int em1 = (tid + 256) >> 3, ej1 = (tid + 256) & 7;

    float creg[2] = {0.f, 0.f};

#pragma unroll 1
    for (int t = 0; t < TSTEPS; ++t) {
        // prefetch this step's xw gate sums into registers
        const float* xwt = xw + (size_t)t * NBATCH * NGATE;
        const float* x0 = xwt + (size_t)em0 * NGATE + hs + ej0;
        const float* x1 = xwt + (size_t)em1 * NGATE + hs + ej1;
        float xr0i = x0[0], xr0f = x0[HID], xr0g = x0[2 * HID], xr0o = x0[3 * HID];
        float xr1i = x1[0], xr1f = x1[HID], xr1g = x1[2 * HID], xr1o = x1[3 * HID];

        float acc[2][4][4];
#pragma unroll
        for (int a = 0; a < 2; ++a)
#pragma unroll
            for (int b = 0; b < 4; ++b)
#pragma unroll
                for (int q = 0; q < 4; ++q) acc[a][b][q] = 0.f;

        if (t > 0) {
            const bf16* pAh = hHi + (size_t)(t - 1) * NBATCH * HID + asrc;
            const bf16* pAl = hLo + (size_t)(t - 1) * NBATCH * HID + asrc;
#define STEP_ISSUE(r, s) do {                                                  \
    _Pragma("unroll")                                                          \
    for (int g2 = 0; g2 < 4; ++g2) {                                           \
        const uint32_t d0 = sb + (uint32_t)g2 * A_G_STRIDE +                   \
                            (uint32_t)(s) * A_ST_STRIDE + adst;                \
        const int ko = (8 * g2 + (r)) * 32;                                    \
        cpa16(d0,          pAh + ko);                                          \
        cpa16(d0 + A_PART, pAl + ko);                                          \
    }                                                                          \
    CP_COMMIT(); } while (0)

            STEP_ISSUE(0, 0);
            STEP_ISSUE(1, 1);
            int cst = 0;                     // stage of round r   (= r%3)
            int ist = 2;                     // stage of round r+2 (= (r+2)%3)
            for (int r = 0; r < 8; ++r) {
                if (r < 7) CP_WAIT1(); else CP_WAIT0();   // group r landed
                __syncthreads();             // readers of round r-1 done
                if (r + 2 < 8) STEP_ISSUE(r + 2, ist);
                const uint32_t ab = aGbase + (uint32_t)cst * A_ST_STRIDE;
                const uint32_t bt = (uint32_t)((8 * kg + r) * 2048);
#pragma unroll
                for (int kk = 0; kk < 2; ++kk) {
                    const uint32_t ca = ac16 + (uint32_t)kk * 32;
                    uint32_t ah0[4], ah1[4], al0[4], al1[4];
                    ldsm4(ah0, ab + SWZ(a_row0 + ca));
                    ldsm4(ah1, ab + SWZ(a_row1 + ca));
                    ldsm4(al0, ab + A_PART + SWZ(a_row0 + ca));
                    ldsm4(al1, ab + A_PART + SWZ(a_row1 + ca));
                    uint32_t bhA[4], bhB[4], blA[4], blB[4];
                    ldsm4(bhA, sb + SM_B_HI + bt + SWZ(b_row0 + ca));
                    ldsm4(bhB, sb + SM_B_HI + bt + SWZ(b_row1 + ca));
                    ldsm4(blA, sb + SM_B_LO + bt + SWZ(b_row0 + ca));
                    ldsm4(blB, sb + SM_B_LO + bt + SWZ(b_row1 + ca));
                    // m-half block 0 (rows mhalf*32 + 0..15)
                    mma_nt(acc[0][0], ah0, bhA[0], bhA[2]);
                    mma_nt(acc[0][0], ah0, blA[0], blA[2]);
                    mma_nt(acc[0][0], al0, bhA[0], bhA[2]);
                    mma_nt(acc[0][1], ah0, bhA[1], bhA[3]);
                    mma_nt(acc[0][1], ah0, blA[1], blA[3]);
                    mma_nt(acc[0][1], al0, bhA[1], bhA[3]);
                    mma_nt(acc[0][2], ah0, bhB[0], bhB[2]);
                    mma_nt(acc[0][2], ah0, blB[0], blB[2]);
                    mma_nt(acc[0][2], al0, bhB[0], bhB[2]);
                    mma_nt(acc[0][3], ah0, bhB[1], bhB[3]);
                    mma_nt(acc[0][3], ah0, blB[1], blB[3]);
                    mma_nt(acc[0][3], al0, bhB[1], bhB[3]);
                    // m-half block 1 (rows mhalf*32 + 16..31)
                    mma_nt(acc[1][0], ah1, bhA[0], bhA[2]);
                    mma_nt(acc[1][0], ah1, blA[0], blA[2]);
                    mma_nt(acc[1][0], al1, bhA[0], bhA[2]);
                    mma_nt(acc[1][1], ah1, bhA[1], bhA[3]);
                    mma_nt(acc[1][1], ah1, blA[1], blA[3]);
                    mma_nt(acc[1][1], al1, bhA[1], bhA[3]);
                    mma_nt(acc[1][2], ah1, bhB[0], bhB[2]);
                    mma_nt(acc[1][2], ah1, blB[0], blB[2]);
                    mma_nt(acc[1][2], al1, bhB[0], bhB[2]);
                    mma_nt(acc[1][3], ah1, bhB[1], bhB[3]);
                    mma_nt(acc[1][3], ah1, blB[1], blB[3]);
                    mma_nt(acc[1][3], al1, bhB[1], bhB[3]);
                }
                cst = cst + 1 == 3 ? 0 : cst + 1;
                ist = ist + 1 == 3 ? 0 : ist + 1;
            }
#undef STEP_ISSUE
        }
        __syncthreads();                     // A region free -> sGp alias safe

        // write split-K partials: sGp[kg][row][col], col = gate*8 + hcol
        {
            const int r0 = mhalf * 32 + (lane >> 2);
            const int c0 = (lane & 3) * 2;
#pragma unroll
            for (int mb = 0; mb < 2; ++mb) {
                const int base = kg * 2112 + (r0 + mb * 16) * 33 + c0;
#pragma unroll
                for (int nb = 0; nb < 4; ++nb) {
                    const int idx = base + nb * 8;
                    sGp[idx]              = acc[mb][nb][0];
                    sGp[idx + 1]          = acc[mb][nb][1];
                    sGp[idx + 8 * 33]     = acc[mb][nb][2];
                    sGp[idx + 8 * 33 + 1] = acc[mb][nb][3];
                }
            }
        }
        __syncthreads();

        // epilogue: 64 batch x 8 h-cols = 512 elements; sum 4 k-group partials
        const size_t obase = (size_t)t * NBATCH * HID;
        {
            const int i0 = em0 * 33 + ej0;
            const float ii = sGp[i0] + sGp[i0 + 2112] + sGp[i0 + 4224] + sGp[i0 + 6336] + xr0i;
            const int i1 = i0 + 8;
            const float ff = sGp[i1] + sGp[i1 + 2112] + sGp[i1 + 4224] + sGp[i1 + 6336] + xr0f;
            const int i2 = i0 + 16;
            const float gg = sGp[i2] + sGp[i2 + 2112] + sGp[i2 + 4224] + sGp[i2 + 6336] + xr0g;
            const int i3 = i0 + 24;
            const float oo = sGp[i3] + sGp[i3 + 2112] + sGp[i3 + 4224] + sGp[i3 + 6336] + xr0o;
            const float c = sigf(ff) * creg[0] + sigf(ii) * tanhf_fast(gg);
            const float h = sigf(oo) * tanhf_fast(c);
            creg[0] = c;
            const bf16 hh = __float2bfloat16(h);
            const size_t oidx = obase + (size_t)em0 * HID + hs + ej0;
            hHi[oidx] = hh;
            hLo[oidx] = __float2bfloat16(h - __bfloat162float(hh));
            if (outF) outF[oidx] = h;
        }
        {
            const int i0 = em1 * 33 + ej1;
            const float ii = sGp[i0] + sGp[i0 + 2112] + sGp[i0 + 4224] + sGp[i0 + 6336] + xr1i;
            const int i1 = i0 + 8;
            const float ff = sGp[i1] + sGp[i1 + 2112] + sGp[i1 + 4224] + sGp[i1 + 6336] + xr1f;
            const int i2 = i0 + 16;
            const float gg = sGp[i2] + sGp[i2 + 2112] + sGp[i2 + 4224] + sGp[i2 + 6336] + xr1g;
            const int i3 = i0 + 24;
            const float oo = sGp[i3] + sGp[i3 + 2112] + sGp[i3 + 4224] + sGp[i3 + 6336] + xr1o;
            const float c = sigf(ff) * creg[1] + sigf(ii) * tanhf_fast(gg);
            const float h = sigf(oo) * tanhf_fast(c);
            creg[1] = c;
            const bf16 hh = __float2bfloat16(h);
            const size_t oidx = obase + (size_t)em1 * HID + hs + ej1;
            hHi[oidx] = hh;
            hLo[oidx] = __float2bfloat16(h - __bfloat162float(hh));
            if (outF) outF[oidx] = h;
        }
        grid_barrier<128>();
    }
}

// ---------------- host ------------------------------------------------------
extern "C" void kernel_launch(void* const* d_in, const int* in_sizes, int n_in,
                              void* d_out, int out_size) {
    const float* x    = (const float*)d_in[0];
    const float* wih0 = (const float*)d_in[1];
    const float* whh0 = (const float*)d_in[2];
    const float* bih0 = (const float*)d_in[3];
    const float* bhh0 = (const float*)d_in[4];
    const float* wih1 = (const float*)d_in[5];
    const float* whh1 = (const float*)d_in[6];
    const float* bih1 = (const float*)d_in[7];
    const float* bhh1 = (const float*)d_in[8];

    float *xw, *bias;
    bf16 *ahi, *alo, *whi, *wlo;
    cudaGetSymbolAddress((void**)&xw,   g_xw);
    cudaGetSymbolAddress((void**)&ahi,  g_ahi);
    cudaGetSymbolAddress((void**)&alo,  g_alo);
    cudaGetSymbolAddress((void**)&whi,  g_whi);
    cudaGetSymbolAddress((void**)&wlo,  g_wlo);
    cudaGetSymbolAddress((void**)&bias, g_bias);

    cudaFuncSetAttribute(lstm_layer, cudaFuncAttributeMaxDynamicSharedMemorySize,
                         SM_LSTM_TOTAL);

    // launch order fixed so ncu (-s 5 -c 1) profiles lstm_layer (layer 1)
    prep_split<<<4096, 256>>>(x, wih0, whh0, wih1, whh1, ahi, alo, whi, wlo);
    prep_bias<<<32, 256>>>(bih0, bhh0, bih1, bhh1, bias);

    for (int layer = 0; layer < 2; ++layer) {
        const size_t wih_off = (size_t)(2 * layer) * GH;
        const size_t whh_off = (size_t)(2 * layer + 1) * GH;
        gemm_xw<<<dim3(64, 512), 256>>>(ahi, alo, whi + wih_off, wlo + wih_off,
                                        bias + layer * NGATE, xw);
        lstm_layer<<<128, 256, SM_LSTM_TOTAL>>>(whi + whh_off, wlo + whh_off, xw,
                                                ahi, alo,
                                                layer ? (float*)d_out : nullptr);
    }
}